// round 5
// baseline (speedup 1.0000x reference)
#include <cuda_runtime.h>
#include <cuda_bf16.h>
#include <cstdint>

#define B_   8
#define N_   1024
#define C_   768
#define H_   12
#define D_   64
#define BH_  96
#define M_   8192
#define O3_  2304
#define FIXCAP (1 << 21)

// Scratch (static __device__ — no allocation in kernel_launch)
__device__ __align__(16) int8_t g_spk[3][BH_][N_][D_];   // q/k/v ternary spikes
__device__ __align__(16) int8_t g_s[M_][C_];             // post-attention spikes
__device__ int    g_flag[M_];                            // per-row spike flag
__device__ int    g_nfix;                                // uncertain-element count
__device__ int    g_fix_list[FIXCAP];                    // packed m*2304+o
__device__ __align__(16) __nv_bfloat16 g_xh[M_ * C_];    // x split hi
__device__ __align__(16) __nv_bfloat16 g_xl[M_ * C_];    // x split lo
__device__ __align__(16) __nv_bfloat16 g_wh[O3_ * C_];   // w_qkv split hi
__device__ __align__(16) __nv_bfloat16 g_wl[O3_ * C_];   // w_qkv split lo

#define MARGIN 8e-4f

__device__ __forceinline__ int spike_of(float v) {
    float u = v + 0.5f;                        // replicate reference op order
    return (u >= 1.0f) ? 1 : ((u < 0.0f) ? -1 : 0);
}

// ---------------------------------------------------------------------------
// Kernel 0: zero flags + fixup counter (graph replays need deterministic init)
// ---------------------------------------------------------------------------
__global__ void init_kernel() {
    int i = blockIdx.x * blockDim.x + threadIdx.x;
    if (i < M_) g_flag[i] = 0;
    if (i == 0) g_nfix = 0;
}

// ---------------------------------------------------------------------------
// Kernel A0: fp32 -> bf16 hi/lo split of x and w_qkv.
// ---------------------------------------------------------------------------
__global__ void __launch_bounds__(256) convert_kernel(const float* __restrict__ x,
                                                      const float* __restrict__ w) {
    const int stride = gridDim.x * blockDim.x;
    const int nx = M_ * C_ / 4, nw = O3_ * C_ / 4;
    for (int j = blockIdx.x * blockDim.x + threadIdx.x; j < nx; j += stride) {
        float4 v = ((const float4*)x)[j];
        float vv[4] = {v.x, v.y, v.z, v.w};
        __nv_bfloat16 h[4], l[4];
#pragma unroll
        for (int i = 0; i < 4; i++) {
            h[i] = __float2bfloat16(vv[i]);
            l[i] = __float2bfloat16(vv[i] - __bfloat162float(h[i]));
        }
        __nv_bfloat162 p0, p1, q0, q1;
        p0.x = h[0]; p0.y = h[1]; p1.x = h[2]; p1.y = h[3];
        q0.x = l[0]; q0.y = l[1]; q1.x = l[2]; q1.y = l[3];
        ((__nv_bfloat162*)g_xh)[2*j]     = p0;
        ((__nv_bfloat162*)g_xh)[2*j + 1] = p1;
        ((__nv_bfloat162*)g_xl)[2*j]     = q0;
        ((__nv_bfloat162*)g_xl)[2*j + 1] = q1;
    }
    for (int j = blockIdx.x * blockDim.x + threadIdx.x; j < nw; j += stride) {
        float4 v = ((const float4*)w)[j];
        float vv[4] = {v.x, v.y, v.z, v.w};
        __nv_bfloat16 h[4], l[4];
#pragma unroll
        for (int i = 0; i < 4; i++) {
            h[i] = __float2bfloat16(vv[i]);
            l[i] = __float2bfloat16(vv[i] - __bfloat162float(h[i]));
        }
        __nv_bfloat162 p0, p1, q0, q1;
        p0.x = h[0]; p0.y = h[1]; p1.x = h[2]; p1.y = h[3];
        q0.x = l[0]; q0.y = l[1]; q1.x = l[2]; q1.y = l[3];
        ((__nv_bfloat162*)g_wh)[2*j]     = p0;
        ((__nv_bfloat162*)g_wh)[2*j + 1] = p1;
        ((__nv_bfloat162*)g_wl)[2*j]     = q0;
        ((__nv_bfloat162*)g_wl)[2*j + 1] = q1;
    }
}

// ---------------------------------------------------------------------------
// Kernel A1: QKV GEMM, mma.sync bf16 split, cp.async double-buffered, LDSM.
// 128x128 tile, BK=32, 8 warps (4M x 2N), warp tile 32x64.
// Dynamic smem: 2 stages x 4 arrays x (128 rows x 80B) = 81920 B.
// ---------------------------------------------------------------------------
#define ARR_B   10240            // bytes per array per stage
#define STG_B   40960            // bytes per stage
#define QKV_DSMEM 81920

__device__ __forceinline__ void mma_bf16(float* c, const int* a, const int* b) {
    asm volatile("mma.sync.aligned.m16n8k16.row.col.f32.bf16.bf16.f32 "
        "{%0,%1,%2,%3}, {%4,%5,%6,%7}, {%8,%9}, {%0,%1,%2,%3};"
        : "+f"(c[0]), "+f"(c[1]), "+f"(c[2]), "+f"(c[3])
        : "r"(a[0]), "r"(a[1]), "r"(a[2]), "r"(a[3]), "r"(b[0]), "r"(b[1]));
}
__device__ __forceinline__ void ldsm_x4(int* r, uint32_t addr) {
    asm volatile("ldmatrix.sync.aligned.m8n8.x4.shared.b16 {%0,%1,%2,%3}, [%4];"
        : "=r"(r[0]), "=r"(r[1]), "=r"(r[2]), "=r"(r[3]) : "r"(addr));
}

__global__ void __launch_bounds__(256) qkv_mma_kernel() {
    extern __shared__ char dyn[];
    uint32_t sbase;
    asm("{ .reg .u64 tmp; cvta.to.shared.u64 tmp, %1; cvt.u32.u64 %0, tmp; }"
        : "=r"(sbase) : "l"(dyn));
    const int t = threadIdx.x, lane = t & 31, wid = t >> 5;
    const int g = lane >> 2, tig = lane & 3;
    const int warpM = wid & 3, warpN = wid >> 2;
    const int o0 = blockIdx.x * 128, m0 = blockIdx.y * 128;

    // per-lane ldmatrix base offsets (bytes)
    const int jA = lane >> 3, rrA = lane & 7;
    const uint32_t offA = (uint32_t)((warpM * 32 + (jA & 1) * 8 + rrA) * 80
                                     + (jA >> 1) * 16);
    const uint32_t offB = (uint32_t)((warpN * 64 + (jA >> 1) * 8 + rrA) * 80
                                     + (jA & 1) * 16);

    float acc[2][8][4] = {};

#define PREFETCH(st, k0) do {                                                  \
    int _s = (st) * STG_B;                                                     \
    _Pragma("unroll")                                                          \
    for (int _c = 0; _c < 2; _c++) {                                           \
        int ch = t + _c * 256;                                                 \
        int row = ch >> 2, qi = ch & 3;                                        \
        uint32_t doff = (uint32_t)(row * 80 + qi * 16);                        \
        size_t ga = (size_t)(m0 + row) * C_ + (k0) + qi * 8;                   \
        size_t gb = (size_t)(o0 + row) * C_ + (k0) + qi * 8;                   \
        asm volatile("cp.async.cg.shared.global [%0], [%1], 16;"               \
                     :: "r"(sbase + _s + doff), "l"(g_xh + ga));               \
        asm volatile("cp.async.cg.shared.global [%0], [%1], 16;"               \
                     :: "r"(sbase + _s + ARR_B + doff), "l"(g_xl + ga));       \
        asm volatile("cp.async.cg.shared.global [%0], [%1], 16;"               \
                     :: "r"(sbase + _s + 2 * ARR_B + doff), "l"(g_wh + gb));   \
        asm volatile("cp.async.cg.shared.global [%0], [%1], 16;"               \
                     :: "r"(sbase + _s + 3 * ARR_B + doff), "l"(g_wl + gb));   \
    } } while (0)

    PREFETCH(0, 0);
    asm volatile("cp.async.commit_group;");

    for (int it = 0; it < 24; it++) {
        if (it + 1 < 24) {
            PREFETCH((it + 1) & 1, (it + 1) * 32);
            asm volatile("cp.async.commit_group;");
            asm volatile("cp.async.wait_group 1;");
        } else {
            asm volatile("cp.async.wait_group 0;");
        }
        __syncthreads();

        const uint32_t stg = sbase + (it & 1) * STG_B;
#pragma unroll
        for (int ks = 0; ks < 2; ks++) {
            int ah[2][4], al[2][4];
#pragma unroll
            for (int mi = 0; mi < 2; mi++) {
                uint32_t aAddr = stg + offA + mi * (16 * 80) + ks * 32;
                ldsm_x4(ah[mi], aAddr);
                ldsm_x4(al[mi], aAddr + ARR_B);
            }
#pragma unroll
            for (int nip = 0; nip < 4; nip++) {
                int bq[4], blq[4];
                uint32_t bAddr = stg + 2 * ARR_B + offB + nip * (16 * 80) + ks * 32;
                ldsm_x4(bq, bAddr);
                ldsm_x4(blq, bAddr + ARR_B);
#pragma unroll
                for (int mi = 0; mi < 2; mi++) {
                    mma_bf16(acc[mi][nip * 2],     ah[mi], bq);
                    mma_bf16(acc[mi][nip * 2],     ah[mi], blq);
                    mma_bf16(acc[mi][nip * 2],     al[mi], bq);
                    mma_bf16(acc[mi][nip * 2 + 1], ah[mi], bq + 2);
                    mma_bf16(acc[mi][nip * 2 + 1], ah[mi], blq + 2);
                    mma_bf16(acc[mi][nip * 2 + 1], al[mi], bq + 2);
                }
            }
        }
        __syncthreads();
    }

    // Epilogue: provisional spikes + warp-aggregated push of uncertain coords
    const int tt = o0 / 768;
    const int h0 = ((o0 % 768) >> 6) + warpN;
    const int bh = (m0 >> 10) * H_ + h0;
    const int nb = (m0 & 1023) + warpM * 32;
#pragma unroll
    for (int mi = 0; mi < 2; mi++) {
#pragma unroll
        for (int ni = 0; ni < 8; ni++) {
            int8_t sv[4];
#pragma unroll
            for (int e = 0; e < 4; e++) {
                float v = acc[mi][ni][e];
                sv[e] = (int8_t)spike_of(v);
                bool unc = (fabsf(v - 0.5f) < MARGIN) || (fabsf(v + 0.5f) < MARGIN);
                unsigned msk = __ballot_sync(0xffffffffu, unc);
                if (msk) {
                    int ldr = __ffs(msk) - 1;
                    int base = 0;
                    if (lane == ldr) base = atomicAdd(&g_nfix, __popc(msk));
                    base = __shfl_sync(0xffffffffu, base, ldr);
                    if (unc) {
                        int mg = m0 + warpM * 32 + mi * 16 + g + ((e >> 1) ? 8 : 0);
                        int og = o0 + warpN * 64 + ni * 8 + tig * 2 + (e & 1);
                        int pos = base + __popc(msk & ((1u << lane) - 1));
                        if (pos < FIXCAP) g_fix_list[pos] = mg * O3_ + og;
                    }
                }
            }
            int n1 = nb + mi * 16 + g;
            int d = ni * 8 + tig * 2;
            char2 v0, v1;
            v0.x = sv[0]; v0.y = sv[1];
            v1.x = sv[2]; v1.y = sv[3];
            *(char2*)&g_spk[tt][bh][n1][d]     = v0;
            *(char2*)&g_spk[tt][bh][n1 + 8][d] = v1;
        }
    }
}

// ---------------------------------------------------------------------------
// Kernel A2: fixup — exact fp32 warp-dots for listed uncertain elements.
// ---------------------------------------------------------------------------
__global__ void __launch_bounds__(256) fixup_kernel(const float* __restrict__ x,
                                                    const float* __restrict__ w) {
    const int lane = threadIdx.x & 31;
    const int gw = (blockIdx.x * blockDim.x + threadIdx.x) >> 5;
    const int nw = (gridDim.x * blockDim.x) >> 5;
    int nfix = g_nfix;
    if (nfix > FIXCAP) nfix = FIXCAP;

    for (int i = gw; i < nfix; i += nw) {
        int code = g_fix_list[i];
        int m = code / O3_;
        int o = code - m * O3_;
        const float4* xp = (const float4*)(x + (size_t)m * C_);
        const float4* wp = (const float4*)(w + (size_t)o * C_);
        float s = 0.0f;
#pragma unroll
        for (int c = 0; c < 6; c++) {
            float4 xv = xp[lane + c * 32];
            float4 wv = wp[lane + c * 32];
            s += xv.x * wv.x + xv.y * wv.y + xv.z * wv.z + xv.w * wv.w;
        }
#pragma unroll
        for (int off = 16; off; off >>= 1)
            s += __shfl_xor_sync(0xffffffffu, s, off);
        if (lane == 0) {
            int tt = o / 768, rem = o - tt * 768;
            g_spk[tt][(m >> 10) * H_ + (rem >> 6)][m & 1023][rem & 63] =
                (int8_t)spike_of(s);
        }
    }
}

// ---------------------------------------------------------------------------
// Kernel B: FUSED attention — s8 IMMA logits into smem (cp.async K tiles),
// then per-row softmax decision + v-row select.
// Dynamic smem: ssq 4KB @0, ssk[2] 4KB @4096/@8192, sd 64x1040 @12288.
// ---------------------------------------------------------------------------
#define ATTN_DSMEM (12288 + 64 * 1040)

__global__ void __launch_bounds__(128) attn_kernel() {
    extern __shared__ char dyn[];
    uint32_t sbase;
    asm("{ .reg .u64 tmp; cvta.to.shared.u64 tmp, %1; cvt.u32.u64 %0, tmp; }"
        : "=r"(sbase) : "l"(dyn));
    char* ssq = dyn;
    char* sd  = dyn + 12288;
    const int t = threadIdx.x;
    const int lane = t & 31, wrp = t >> 5;
    const int gid = lane >> 2, tig = lane & 3;
    const int bh = blockIdx.y, n0 = blockIdx.x * 64;
    const int b = bh / H_, h = bh - b * H_;

#define KPRE(mc, buf) do {                                                     \
    const int8_t* _src = &g_spk[1][bh][(mc) * 64][0] + t * 32;                 \
    uint32_t _dst = sbase + 4096 + (buf) * 4096 + t * 32;                      \
    asm volatile("cp.async.cg.shared.global [%0], [%1], 16;"                   \
                 :: "r"(_dst), "l"(_src));                                     \
    asm volatile("cp.async.cg.shared.global [%0], [%1], 16;"                   \
                 :: "r"(_dst + 16), "l"(_src + 16));                           \
    } while (0)

    {
        const int4* src = (const int4*)&g_spk[0][bh][n0][0];
        int4* dst = (int4*)ssq;
        dst[t] = src[t]; dst[t + 128] = src[t + 128];
    }
    KPRE(0, 0);
    asm volatile("cp.async.commit_group;");
    __syncthreads();

    int afr[2][4];
#pragma unroll
    for (int ks = 0; ks < 2; ks++) {
        int r = wrp * 16 + gid;
        afr[ks][0] = *(const int*)(ssq + r * 64 + ks * 32 + tig * 4);
        afr[ks][1] = *(const int*)(ssq + (r + 8) * 64 + ks * 32 + tig * 4);
        afr[ks][2] = *(const int*)(ssq + r * 64 + ks * 32 + 16 + tig * 4);
        afr[ks][3] = *(const int*)(ssq + (r + 8) * 64 + ks * 32 + 16 + tig * 4);
    }

    for (int mc = 0; mc < 16; mc++) {
        if (mc + 1 < 16) {
            KPRE(mc + 1, (mc + 1) & 1);
            asm volatile("cp.async.commit_group;");
            asm volatile("cp.async.wait_group 1;");
        } else {
            asm volatile("cp.async.wait_group 0;");
        }
        __syncthreads();
        const char* ssk = dyn + 4096 + (mc & 1) * 4096;
#pragma unroll
        for (int c = 0; c < 8; c++) {
            int c0 = 0, c1 = 0, c2 = 0, c3 = 0;
#pragma unroll
            for (int ks = 0; ks < 2; ks++) {
                int b0 = *(const int*)(ssk + (c * 8 + gid) * 64 + ks * 32 + tig * 4);
                int b1 = *(const int*)(ssk + (c * 8 + gid) * 64 + ks * 32 + 16 + tig * 4);
                asm volatile(
                    "mma.sync.aligned.m16n8k32.row.col.s32.s8.s8.s32 "
                    "{%0,%1,%2,%3}, {%4,%5,%6,%7}, {%8,%9}, {%0,%1,%2,%3};"
                    : "+r"(c0), "+r"(c1), "+r"(c2), "+r"(c3)
                    : "r"(afr[ks][0]), "r"(afr[ks][1]), "r"(afr[ks][2]), "r"(afr[ks][3]),
                      "r"(b0), "r"(b1));
            }
            int row = wrp * 16 + gid;
            int col = mc * 64 + c * 8 + tig * 2;
            char2 lo; lo.x = (char)c0; lo.y = (char)c1;
            char2 hi; hi.x = (char)c2; hi.y = (char)c3;
            *(char2*)(sd + row * 1040 + col)       = lo;
            *(char2*)(sd + (row + 8) * 1040 + col) = hi;
        }
        __syncthreads();
    }

    // Phase 2: each warp reduces 16 rows
    for (int r = 0; r < 16; r++) {
        const int row = wrp * 16 + r;
        const char* rp = sd + row * 1040;
        int4 v0 = ((const int4*)rp)[lane];
        int4 v1 = ((const int4*)rp)[lane + 32];
        int words[8] = {v0.x, v0.y, v0.z, v0.w, v1.x, v1.y, v1.z, v1.w};

        // SIMD byte max
        int mxw = words[0];
#pragma unroll
        for (int wi = 1; wi < 8; wi++) mxw = __vmaxs4(mxw, words[wi]);
#pragma unroll
        for (int off = 16; off; off >>= 1)
            mxw = __vmaxs4(mxw, __shfl_xor_sync(0xffffffffu, mxw, off));
        int lmax = max(max((mxw << 24) >> 24, (mxw << 16) >> 24),
                       max((mxw << 8) >> 24,  mxw >> 24));

        // cheap reject: count elements >= lmax - 8 (each contributes >= e^-1)
        int t8 = lmax - 8;
        int tspl = (t8 & 0xff) * 0x01010101;
        int cnt = 0;
#pragma unroll
        for (int wi = 0; wi < 8; wi++)
            cnt += __popc(__vcmpges4(words[wi], tspl));
#pragma unroll
        for (int off = 16; off; off >>= 1)
            cnt += __shfl_xor_sync(0xffffffffu, cnt, off);

        int* dst = (int*)&g_s[b * N_ + n0 + row][h * D_];
        if (cnt >= 32) {        // >= 4 elems -> s >= 1 + 3/e = 2.10 > 2: no spike
            if (lane < 16) dst[lane] = 0;
            continue;
        }

        // exact path (rare): argmax + precise expf sum, matches reference math
        float s = 0.0f;
        int larg = 0x7fffffff;
#pragma unroll
        for (int wi = 0; wi < 8; wi++) {
            int colbase = (wi < 4) ? (lane * 16 + wi * 4)
                                   : (512 + lane * 16 + (wi - 4) * 4);
#pragma unroll
            for (int j = 0; j < 4; j++) {
                int val = (words[wi] << (24 - 8 * j)) >> 24;
                s += expf(0.125f * (float)(val - lmax));
                if (val == lmax) larg = min(larg, colbase + j);
            }
        }
#pragma unroll
        for (int off = 16; off; off >>= 1) {
            s    += __shfl_xor_sync(0xffffffffu, s, off);
            larg  = min(larg, __shfl_xor_sync(0xffffffffu, larg, off));
        }
        float p = 1.0f / s;
        bool spk = (p + 0.5f) >= 1.0f;
        if (spk) {
            const int* src = (const int*)&g_spk[2][bh][larg][0];
            if (lane < 16) dst[lane] = src[lane];
            if (lane == 0) g_flag[b * N_ + n0 + row] = 1;
        } else {
            if (lane < 16) dst[lane] = 0;
        }
    }
}

// ---------------------------------------------------------------------------
// Kernel C: output projection (fp32 exact) + final IF, zero-tile skip.
// ---------------------------------------------------------------------------
__global__ void __launch_bounds__(256) proj_kernel(const float* __restrict__ wp,
                                                   float* __restrict__ out) {
    __shared__ float As[16][64];
    __shared__ float Bs[16][64];
    __shared__ int s_any;
    const int t = threadIdx.x;
    const int tx = t & 15, ty = t >> 4;
    const int m0 = blockIdx.y * 64, o0 = blockIdx.x * 64;
    const int lr = t >> 2, lc = (t & 3) * 4;

    if (t == 0) s_any = 0;
    __syncthreads();
    if (t < 64 && g_flag[m0 + t]) s_any = 1;
    __syncthreads();
    if (!s_any) {
        float4 z = make_float4(0.f, 0.f, 0.f, 0.f);
#pragma unroll
        for (int p = 0; p < 4; p++)
            *(float4*)&out[(size_t)(m0 + lr) * 768 + o0 + (t & 3) * 4 + p * 16] = z;
        return;
    }

    float acc[4][4] = {};
    for (int k0 = 0; k0 < 768; k0 += 16) {
        int    aw = *(const int*)&g_s[m0 + lr][k0 + lc];
        float4 bv = *(const float4*)&wp[(size_t)(o0 + lr) * 768 + k0 + lc];
        __syncthreads();
        As[lc + 0][lr] = (float)((aw << 24) >> 24);
        As[lc + 1][lr] = (float)((aw << 16) >> 24);
        As[lc + 2][lr] = (float)((aw << 8)  >> 24);
        As[lc + 3][lr] = (float)( aw        >> 24);
        Bs[lc + 0][lr] = bv.x; Bs[lc + 1][lr] = bv.y;
        Bs[lc + 2][lr] = bv.z; Bs[lc + 3][lr] = bv.w;
        __syncthreads();
#pragma unroll
        for (int k = 0; k < 16; k++) {
            float4 a = *(const float4*)&As[k][ty * 4];
            float4 b = *(const float4*)&Bs[k][tx * 4];
            float ar[4] = {a.x, a.y, a.z, a.w};
            float br[4] = {b.x, b.y, b.z, b.w};
#pragma unroll
            for (int i = 0; i < 4; i++)
#pragma unroll
                for (int j = 0; j < 4; j++)
                    acc[i][j] = fmaf(ar[i], br[j], acc[i][j]);
        }
    }
#pragma unroll
    for (int i = 0; i < 4; i++) {
        int m = m0 + ty * 4 + i;
#pragma unroll
        for (int j = 0; j < 4; j++) {
            int o = o0 + tx * 4 + j;
            out[(size_t)m * 768 + o] = (float)spike_of(acc[i][j]);
        }
    }
}

// ---------------------------------------------------------------------------
extern "C" void kernel_launch(void* const* d_in, const int* in_sizes, int n_in,
                              void* d_out, int out_size) {
    const float* x      = (const float*)d_in[0];
    const float* w_qkv  = (const float*)d_in[1];
    const float* w_proj = (const float*)d_in[2];
    float* out = (float*)d_out;

    cudaFuncSetAttribute(qkv_mma_kernel,
                         cudaFuncAttributeMaxDynamicSharedMemorySize, QKV_DSMEM);
    cudaFuncSetAttribute(attn_kernel,
                         cudaFuncAttributeMaxDynamicSharedMemorySize, ATTN_DSMEM);

    init_kernel<<<8, 1024>>>();
    convert_kernel<<<960, 256>>>(x, w_qkv);
    qkv_mma_kernel<<<dim3(18, 64), 256, QKV_DSMEM>>>();
    fixup_kernel<<<512, 256>>>(x, w_qkv);
    attn_kernel<<<dim3(16, 96), 128, ATTN_DSMEM>>>();
    proj_kernel<<<dim3(12, 128), 256>>>(w_proj, out);
}

// round 6
// speedup vs baseline: 1.2048x; 1.2048x over previous
#include <cuda_runtime.h>
#include <cuda_bf16.h>
#include <cstdint>

#define B_   8
#define N_   1024
#define C_   768
#define H_   12
#define D_   64
#define BH_  96
#define M_   8192
#define O3_  2304
#define FIXCAP (1 << 21)

// Scratch (static __device__ — no allocation in kernel_launch)
__device__ __align__(16) int8_t g_spk[3][BH_][N_][D_];   // q/k/v ternary spikes
__device__ __align__(16) int8_t g_s[M_][C_];             // post-attention spikes
__device__ int    g_flag[M_];                            // per-row spike flag
__device__ int    g_nfix;                                // uncertain-element count
__device__ int    g_fix_list[FIXCAP];                    // packed m*2304+o
__device__ __align__(16) __nv_bfloat16 g_xh[M_ * C_];    // x split hi
__device__ __align__(16) __nv_bfloat16 g_xl[M_ * C_];    // x split lo
__device__ __align__(16) __nv_bfloat16 g_wh[O3_ * C_];   // w_qkv split hi
__device__ __align__(16) __nv_bfloat16 g_wl[O3_ * C_];   // w_qkv split lo

#define MARGIN 8e-4f

__device__ __forceinline__ int spike_of(float v) {
    float u = v + 0.5f;                        // replicate reference op order
    return (u >= 1.0f) ? 1 : ((u < 0.0f) ? -1 : 0);
}

// ---------------------------------------------------------------------------
// Kernel 0: zero flags + fixup counter (graph replays need deterministic init)
// ---------------------------------------------------------------------------
__global__ void init_kernel() {
    int i = blockIdx.x * blockDim.x + threadIdx.x;
    if (i < M_) g_flag[i] = 0;
    if (i == 0) g_nfix = 0;
}

// ---------------------------------------------------------------------------
// Kernel A0: fp32 -> bf16 hi/lo split of x and w_qkv.
// ---------------------------------------------------------------------------
__global__ void __launch_bounds__(256) convert_kernel(const float* __restrict__ x,
                                                      const float* __restrict__ w) {
    const int stride = gridDim.x * blockDim.x;
    const int nx = M_ * C_ / 4, nw = O3_ * C_ / 4;
    for (int j = blockIdx.x * blockDim.x + threadIdx.x; j < nx; j += stride) {
        float4 v = ((const float4*)x)[j];
        float vv[4] = {v.x, v.y, v.z, v.w};
        __nv_bfloat16 h[4], l[4];
#pragma unroll
        for (int i = 0; i < 4; i++) {
            h[i] = __float2bfloat16(vv[i]);
            l[i] = __float2bfloat16(vv[i] - __bfloat162float(h[i]));
        }
        __nv_bfloat162 p0, p1, q0, q1;
        p0.x = h[0]; p0.y = h[1]; p1.x = h[2]; p1.y = h[3];
        q0.x = l[0]; q0.y = l[1]; q1.x = l[2]; q1.y = l[3];
        ((__nv_bfloat162*)g_xh)[2*j]     = p0;
        ((__nv_bfloat162*)g_xh)[2*j + 1] = p1;
        ((__nv_bfloat162*)g_xl)[2*j]     = q0;
        ((__nv_bfloat162*)g_xl)[2*j + 1] = q1;
    }
    for (int j = blockIdx.x * blockDim.x + threadIdx.x; j < nw; j += stride) {
        float4 v = ((const float4*)w)[j];
        float vv[4] = {v.x, v.y, v.z, v.w};
        __nv_bfloat16 h[4], l[4];
#pragma unroll
        for (int i = 0; i < 4; i++) {
            h[i] = __float2bfloat16(vv[i]);
            l[i] = __float2bfloat16(vv[i] - __bfloat162float(h[i]));
        }
        __nv_bfloat162 p0, p1, q0, q1;
        p0.x = h[0]; p0.y = h[1]; p1.x = h[2]; p1.y = h[3];
        q0.x = l[0]; q0.y = l[1]; q1.x = l[2]; q1.y = l[3];
        ((__nv_bfloat162*)g_wh)[2*j]     = p0;
        ((__nv_bfloat162*)g_wh)[2*j + 1] = p1;
        ((__nv_bfloat162*)g_wl)[2*j]     = q0;
        ((__nv_bfloat162*)g_wl)[2*j + 1] = q1;
    }
}

// ---------------------------------------------------------------------------
// Kernel A1: QKV GEMM, mma.sync bf16 split, cp.async double-buffered.
// 128x128 tile, BK=32, 8 warps (4M x 2N), warp tile 32x64.  (R4-proven form)
// Dynamic smem: 2 stages x 4 arrays x (128 rows x 80B) = 81920 B.
// ---------------------------------------------------------------------------
#define ASTRIDE 20               // ints per smem row (16 data + 4 pad)
#define ARR_B   10240            // bytes per array per stage
#define STG_B   40960            // bytes per stage
#define QKV_DSMEM 81920

__device__ __forceinline__ void mma_bf16(float* c, const int* a, const int* b) {
    asm volatile("mma.sync.aligned.m16n8k16.row.col.f32.bf16.bf16.f32 "
        "{%0,%1,%2,%3}, {%4,%5,%6,%7}, {%8,%9}, {%0,%1,%2,%3};"
        : "+f"(c[0]), "+f"(c[1]), "+f"(c[2]), "+f"(c[3])
        : "r"(a[0]), "r"(a[1]), "r"(a[2]), "r"(a[3]), "r"(b[0]), "r"(b[1]));
}

__global__ void __launch_bounds__(256) qkv_mma_kernel() {
    extern __shared__ char dyn[];
    uint32_t sbase;
    asm("{ .reg .u64 tmp; cvta.to.shared.u64 tmp, %1; cvt.u32.u64 %0, tmp; }"
        : "=r"(sbase) : "l"(dyn));
    const int t = threadIdx.x, lane = t & 31, wid = t >> 5;
    const int g = lane >> 2, tig = lane & 3;
    const int warpM = wid & 3, warpN = wid >> 2;
    const int o0 = blockIdx.x * 128, m0 = blockIdx.y * 128;

    float acc[2][8][4] = {};

#define PREFETCH(st, k0) do {                                                  \
    int _s = (st) * STG_B;                                                     \
    _Pragma("unroll")                                                          \
    for (int _c = 0; _c < 2; _c++) {                                           \
        int ch = t + _c * 256;                                                 \
        int row = ch >> 2, qi = ch & 3;                                        \
        uint32_t doff = (uint32_t)(row * 80 + qi * 16);                        \
        size_t ga = (size_t)(m0 + row) * C_ + (k0) + qi * 8;                   \
        size_t gb = (size_t)(o0 + row) * C_ + (k0) + qi * 8;                   \
        asm volatile("cp.async.cg.shared.global [%0], [%1], 16;"               \
                     :: "r"(sbase + _s + doff), "l"(g_xh + ga));               \
        asm volatile("cp.async.cg.shared.global [%0], [%1], 16;"               \
                     :: "r"(sbase + _s + ARR_B + doff), "l"(g_xl + ga));       \
        asm volatile("cp.async.cg.shared.global [%0], [%1], 16;"               \
                     :: "r"(sbase + _s + 2 * ARR_B + doff), "l"(g_wh + gb));   \
        asm volatile("cp.async.cg.shared.global [%0], [%1], 16;"               \
                     :: "r"(sbase + _s + 3 * ARR_B + doff), "l"(g_wl + gb));   \
    } } while (0)

    PREFETCH(0, 0);
    asm volatile("cp.async.commit_group;");

    for (int it = 0; it < 24; it++) {
        if (it + 1 < 24) {
            PREFETCH((it + 1) & 1, (it + 1) * 32);
            asm volatile("cp.async.commit_group;");
            asm volatile("cp.async.wait_group 1;");
        } else {
            asm volatile("cp.async.wait_group 0;");
        }
        __syncthreads();

        const int* pAh = (const int*)(dyn + (it & 1) * STG_B);
        const int* pAl = (const int*)(dyn + (it & 1) * STG_B + ARR_B);
        const int* pBh = (const int*)(dyn + (it & 1) * STG_B + 2 * ARR_B);
        const int* pBl = (const int*)(dyn + (it & 1) * STG_B + 3 * ARR_B);
#pragma unroll
        for (int ks = 0; ks < 2; ks++) {
            int ah[2][4], al[2][4];
#pragma unroll
            for (int mi = 0; mi < 2; mi++) {
                int r0 = (warpM * 32 + mi * 16 + g) * ASTRIDE + ks * 8 + tig;
                ah[mi][0] = pAh[r0];
                ah[mi][1] = pAh[r0 + 8 * ASTRIDE];
                ah[mi][2] = pAh[r0 + 4];
                ah[mi][3] = pAh[r0 + 8 * ASTRIDE + 4];
                al[mi][0] = pAl[r0];
                al[mi][1] = pAl[r0 + 8 * ASTRIDE];
                al[mi][2] = pAl[r0 + 4];
                al[mi][3] = pAl[r0 + 8 * ASTRIDE + 4];
            }
#pragma unroll
            for (int ni = 0; ni < 8; ni++) {
                int rb = (warpN * 64 + ni * 8 + g) * ASTRIDE + ks * 8 + tig;
                int bhf[2] = { pBh[rb], pBh[rb + 4] };
                int blf[2] = { pBl[rb], pBl[rb + 4] };
#pragma unroll
                for (int mi = 0; mi < 2; mi++) {
                    mma_bf16(acc[mi][ni], ah[mi], bhf);
                    mma_bf16(acc[mi][ni], ah[mi], blf);
                    mma_bf16(acc[mi][ni], al[mi], bhf);
                }
            }
        }
        __syncthreads();
    }

    // Epilogue: provisional spikes + warp-aggregated push of uncertain coords
    const int tt = o0 / 768;
    const int h0 = ((o0 % 768) >> 6) + warpN;
    const int bh = (m0 >> 10) * H_ + h0;
    const int nb = (m0 & 1023) + warpM * 32;
#pragma unroll
    for (int mi = 0; mi < 2; mi++) {
#pragma unroll
        for (int ni = 0; ni < 8; ni++) {
            int8_t sv[4];
#pragma unroll
            for (int e = 0; e < 4; e++) {
                float v = acc[mi][ni][e];
                sv[e] = (int8_t)spike_of(v);
                bool unc = (fabsf(v - 0.5f) < MARGIN) || (fabsf(v + 0.5f) < MARGIN);
                unsigned msk = __ballot_sync(0xffffffffu, unc);
                if (msk) {
                    int ldr = __ffs(msk) - 1;
                    int base = 0;
                    if (lane == ldr) base = atomicAdd(&g_nfix, __popc(msk));
                    base = __shfl_sync(0xffffffffu, base, ldr);
                    if (unc) {
                        int mg = m0 + warpM * 32 + mi * 16 + g + ((e >> 1) ? 8 : 0);
                        int og = o0 + warpN * 64 + ni * 8 + tig * 2 + (e & 1);
                        int pos = base + __popc(msk & ((1u << lane) - 1));
                        if (pos < FIXCAP) g_fix_list[pos] = mg * O3_ + og;
                    }
                }
            }
            int n1 = nb + mi * 16 + g;
            int d = ni * 8 + tig * 2;
            char2 v0, v1;
            v0.x = sv[0]; v0.y = sv[1];
            v1.x = sv[2]; v1.y = sv[3];
            *(char2*)&g_spk[tt][bh][n1][d]     = v0;
            *(char2*)&g_spk[tt][bh][n1 + 8][d] = v1;
        }
    }
}

// ---------------------------------------------------------------------------
// Kernel A2: fixup — exact fp32 warp-dots for listed uncertain elements.
// (R5-proven: MARGIN 8e-4 list + float4 loads, 17.2us measured)
// ---------------------------------------------------------------------------
__global__ void __launch_bounds__(256) fixup_kernel(const float* __restrict__ x,
                                                    const float* __restrict__ w) {
    const int lane = threadIdx.x & 31;
    const int gw = (blockIdx.x * blockDim.x + threadIdx.x) >> 5;
    const int nw = (gridDim.x * blockDim.x) >> 5;
    int nfix = g_nfix;
    if (nfix > FIXCAP) nfix = FIXCAP;

    for (int i = gw; i < nfix; i += nw) {
        int code = g_fix_list[i];
        int m = code / O3_;
        int o = code - m * O3_;
        const float4* xp = (const float4*)(x + (size_t)m * C_);
        const float4* wp = (const float4*)(w + (size_t)o * C_);
        float s = 0.0f;
#pragma unroll
        for (int c = 0; c < 6; c++) {
            float4 xv = xp[lane + c * 32];
            float4 wv = wp[lane + c * 32];
            s += xv.x * wv.x + xv.y * wv.y + xv.z * wv.z + xv.w * wv.w;
        }
#pragma unroll
        for (int off = 16; off; off >>= 1)
            s += __shfl_xor_sync(0xffffffffu, s, off);
        if (lane == 0) {
            int tt = o / 768, rem = o - tt * 768;
            g_spk[tt][(m >> 10) * H_ + (rem >> 6)][m & 1023][rem & 63] =
                (int8_t)spike_of(s);
        }
    }
}

// ---------------------------------------------------------------------------
// Kernel B: FUSED attention — s8 IMMA logits into smem, then per-row
// softmax decision + v-row select.  (R4-proven form)
// Dynamic smem: ssq 4KB @0, ssk 4KB @4096, sd 64 x 1040B @8192.
// ---------------------------------------------------------------------------
#define ATTN_DSMEM (8192 + 64 * 1040)

__global__ void __launch_bounds__(128) attn_kernel() {
    extern __shared__ char dyn[];
    char* ssq = dyn;
    char* ssk = dyn + 4096;
    char* sd  = dyn + 8192;
    const int t = threadIdx.x;
    const int lane = t & 31, wrp = t >> 5;
    const int gid = lane >> 2, tig = lane & 3;
    const int bh = blockIdx.y, n0 = blockIdx.x * 64;
    const int b = bh / H_, h = bh - b * H_;

    {
        const int4* src = (const int4*)&g_spk[0][bh][n0][0];
        int4* dst = (int4*)ssq;
        dst[t] = src[t]; dst[t + 128] = src[t + 128];
    }
    __syncthreads();

    int afr[2][4];
#pragma unroll
    for (int ks = 0; ks < 2; ks++) {
        int r = wrp * 16 + gid;
        afr[ks][0] = *(const int*)(ssq + r * 64 + ks * 32 + tig * 4);
        afr[ks][1] = *(const int*)(ssq + (r + 8) * 64 + ks * 32 + tig * 4);
        afr[ks][2] = *(const int*)(ssq + r * 64 + ks * 32 + 16 + tig * 4);
        afr[ks][3] = *(const int*)(ssq + (r + 8) * 64 + ks * 32 + 16 + tig * 4);
    }

    for (int mc = 0; mc < 16; mc++) {
        __syncthreads();
        {
            const int4* src = (const int4*)&g_spk[1][bh][mc * 64][0];
            int4* dst = (int4*)ssk;
            dst[t] = src[t]; dst[t + 128] = src[t + 128];
        }
        __syncthreads();
#pragma unroll
        for (int c = 0; c < 8; c++) {
            int c0 = 0, c1 = 0, c2 = 0, c3 = 0;
#pragma unroll
            for (int ks = 0; ks < 2; ks++) {
                int b0 = *(const int*)(ssk + (c * 8 + gid) * 64 + ks * 32 + tig * 4);
                int b1 = *(const int*)(ssk + (c * 8 + gid) * 64 + ks * 32 + 16 + tig * 4);
                asm volatile(
                    "mma.sync.aligned.m16n8k32.row.col.s32.s8.s8.s32 "
                    "{%0,%1,%2,%3}, {%4,%5,%6,%7}, {%8,%9}, {%0,%1,%2,%3};"
                    : "+r"(c0), "+r"(c1), "+r"(c2), "+r"(c3)
                    : "r"(afr[ks][0]), "r"(afr[ks][1]), "r"(afr[ks][2]), "r"(afr[ks][3]),
                      "r"(b0), "r"(b1));
            }
            int row = wrp * 16 + gid;
            int col = mc * 64 + c * 8 + tig * 2;
            char2 lo; lo.x = (char)c0; lo.y = (char)c1;
            char2 hi; hi.x = (char)c2; hi.y = (char)c3;
            *(char2*)(sd + row * 1040 + col)       = lo;
            *(char2*)(sd + (row + 8) * 1040 + col) = hi;
        }
    }
    __syncthreads();

    // Phase 2: each warp reduces 16 rows
    for (int r = 0; r < 16; r++) {
        const int row = wrp * 16 + r;
        const char* rp = sd + row * 1040;
        int4 v0 = ((const int4*)rp)[lane];
        int4 v1 = ((const int4*)rp)[lane + 32];
        int words[8] = {v0.x, v0.y, v0.z, v0.w, v1.x, v1.y, v1.z, v1.w};

        // SIMD byte max
        int mxw = words[0];
#pragma unroll
        for (int wi = 1; wi < 8; wi++) mxw = __vmaxs4(mxw, words[wi]);
#pragma unroll
        for (int off = 16; off; off >>= 1)
            mxw = __vmaxs4(mxw, __shfl_xor_sync(0xffffffffu, mxw, off));
        int lmax = max(max((mxw << 24) >> 24, (mxw << 16) >> 24),
                       max((mxw << 8) >> 24,  mxw >> 24));

        // cheap reject: count elements >= lmax - 8 (each contributes >= e^-1)
        int t8 = lmax - 8;
        int tspl = (t8 & 0xff) * 0x01010101;
        int cnt = 0;
#pragma unroll
        for (int wi = 0; wi < 8; wi++)
            cnt += __popc(__vcmpges4(words[wi], tspl));
#pragma unroll
        for (int off = 16; off; off >>= 1)
            cnt += __shfl_xor_sync(0xffffffffu, cnt, off);

        int* dst = (int*)&g_s[b * N_ + n0 + row][h * D_];
        if (cnt >= 32) {        // >= 4 elems -> s >= 1 + 3/e = 2.10 > 2: no spike
            if (lane < 16) dst[lane] = 0;
            continue;
        }

        // exact path (rare): argmax + precise expf sum, matches reference math
        float s = 0.0f;
        int larg = 0x7fffffff;
#pragma unroll
        for (int wi = 0; wi < 8; wi++) {
            int colbase = (wi < 4) ? (lane * 16 + wi * 4)
                                   : (512 + lane * 16 + (wi - 4) * 4);
#pragma unroll
            for (int j = 0; j < 4; j++) {
                int val = (words[wi] << (24 - 8 * j)) >> 24;
                s += expf(0.125f * (float)(val - lmax));
                if (val == lmax) larg = min(larg, colbase + j);
            }
        }
#pragma unroll
        for (int off = 16; off; off >>= 1) {
            s    += __shfl_xor_sync(0xffffffffu, s, off);
            larg  = min(larg, __shfl_xor_sync(0xffffffffu, larg, off));
        }
        float p = 1.0f / s;
        bool spk = (p + 0.5f) >= 1.0f;
        if (spk) {
            const int* src = (const int*)&g_spk[2][bh][larg][0];
            if (lane < 16) dst[lane] = src[lane];
            if (lane == 0) g_flag[b * N_ + n0 + row] = 1;
        } else {
            if (lane < 16) dst[lane] = 0;
        }
    }
}

// ---------------------------------------------------------------------------
// Kernel C: output projection (fp32 exact) + final IF, zero-tile skip.
// ---------------------------------------------------------------------------
__global__ void __launch_bounds__(256) proj_kernel(const float* __restrict__ wp,
                                                   float* __restrict__ out) {
    __shared__ float As[16][64];
    __shared__ float Bs[16][64];
    __shared__ int s_any;
    const int t = threadIdx.x;
    const int tx = t & 15, ty = t >> 4;
    const int m0 = blockIdx.y * 64, o0 = blockIdx.x * 64;
    const int lr = t >> 2, lc = (t & 3) * 4;

    if (t == 0) s_any = 0;
    __syncthreads();
    if (t < 64 && g_flag[m0 + t]) s_any = 1;
    __syncthreads();
    if (!s_any) {
        float4 z = make_float4(0.f, 0.f, 0.f, 0.f);
#pragma unroll
        for (int p = 0; p < 4; p++)
            *(float4*)&out[(size_t)(m0 + lr) * 768 + o0 + (t & 3) * 4 + p * 16] = z;
        return;
    }

    float acc[4][4] = {};
    for (int k0 = 0; k0 < 768; k0 += 16) {
        int    aw = *(const int*)&g_s[m0 + lr][k0 + lc];
        float4 bv = *(const float4*)&wp[(size_t)(o0 + lr) * 768 + k0 + lc];
        __syncthreads();
        As[lc + 0][lr] = (float)((aw << 24) >> 24);
        As[lc + 1][lr] = (float)((aw << 16) >> 24);
        As[lc + 2][lr] = (float)((aw << 8)  >> 24);
        As[lc + 3][lr] = (float)( aw        >> 24);
        Bs[lc + 0][lr] = bv.x; Bs[lc + 1][lr] = bv.y;
        Bs[lc + 2][lr] = bv.z; Bs[lc + 3][lr] = bv.w;
        __syncthreads();
#pragma unroll
        for (int k = 0; k < 16; k++) {
            float4 a = *(const float4*)&As[k][ty * 4];
            float4 b = *(const float4*)&Bs[k][tx * 4];
            float ar[4] = {a.x, a.y, a.z, a.w};
            float br[4] = {b.x, b.y, b.z, b.w};
#pragma unroll
            for (int i = 0; i < 4; i++)
#pragma unroll
                for (int j = 0; j < 4; j++)
                    acc[i][j] = fmaf(ar[i], br[j], acc[i][j]);
        }
    }
#pragma unroll
    for (int i = 0; i < 4; i++) {
        int m = m0 + ty * 4 + i;
#pragma unroll
        for (int j = 0; j < 4; j++) {
            int o = o0 + tx * 4 + j;
            out[(size_t)m * 768 + o] = (float)spike_of(acc[i][j]);
        }
    }
}

// ---------------------------------------------------------------------------
extern "C" void kernel_launch(void* const* d_in, const int* in_sizes, int n_in,
                              void* d_out, int out_size) {
    const float* x      = (const float*)d_in[0];
    const float* w_qkv  = (const float*)d_in[1];
    const float* w_proj = (const float*)d_in[2];
    float* out = (float*)d_out;

    cudaFuncSetAttribute(qkv_mma_kernel,
                         cudaFuncAttributeMaxDynamicSharedMemorySize, QKV_DSMEM);
    cudaFuncSetAttribute(attn_kernel,
                         cudaFuncAttributeMaxDynamicSharedMemorySize, ATTN_DSMEM);

    init_kernel<<<8, 1024>>>();
    convert_kernel<<<960, 256>>>(x, w_qkv);
    qkv_mma_kernel<<<dim3(18, 64), 256, QKV_DSMEM>>>();
    fixup_kernel<<<512, 256>>>(x, w_qkv);
    attn_kernel<<<dim3(16, 96), 128, ATTN_DSMEM>>>();
    proj_kernel<<<dim3(12, 128), 256>>>(w_proj, out);
}

// round 7
// speedup vs baseline: 1.2224x; 1.0146x over previous
#include <cuda_runtime.h>
#include <cuda_bf16.h>
#include <cstdint>

#define B_   8
#define N_   1024
#define C_   768
#define H_   12
#define D_   64
#define BH_  96
#define M_   8192
#define O3_  2304
#define FIXCAP (1 << 21)

// Scratch (static __device__ — no allocation in kernel_launch)
__device__ __align__(16) int8_t g_spk[3][BH_][N_][D_];   // q/k/v ternary spikes
__device__ __align__(16) int8_t g_s[M_][C_];             // post-attention spikes
__device__ int    g_flag[M_];                            // per-row spike flag
__device__ int    g_nfix;                                // uncertain-element count
__device__ int    g_fix_list[FIXCAP];                    // packed m*2304+o
__device__ __align__(16) __nv_bfloat16 g_xh[M_ * C_];    // x split hi
__device__ __align__(16) __nv_bfloat16 g_xl[M_ * C_];    // x split lo
__device__ __align__(16) __nv_bfloat16 g_wh[O3_ * C_];   // w_qkv split hi
__device__ __align__(16) __nv_bfloat16 g_wl[O3_ * C_];   // w_qkv split lo

#define MARGIN 4e-4f

__device__ __forceinline__ int spike_of(float v) {
    float u = v + 0.5f;                        // replicate reference op order
    return (u >= 1.0f) ? 1 : ((u < 0.0f) ? -1 : 0);
}

// ---------------------------------------------------------------------------
// Kernel 0: zero flags + fixup counter (graph replays need deterministic init)
// ---------------------------------------------------------------------------
__global__ void init_kernel() {
    int i = blockIdx.x * blockDim.x + threadIdx.x;
    if (i < M_) g_flag[i] = 0;
    if (i == 0) g_nfix = 0;
}

// ---------------------------------------------------------------------------
// Kernel A0: fp32 -> bf16 hi/lo split of x and w_qkv.
// ---------------------------------------------------------------------------
__global__ void __launch_bounds__(256) convert_kernel(const float* __restrict__ x,
                                                      const float* __restrict__ w) {
    const int stride = gridDim.x * blockDim.x;
    const int nx = M_ * C_ / 4, nw = O3_ * C_ / 4;
    for (int j = blockIdx.x * blockDim.x + threadIdx.x; j < nx; j += stride) {
        float4 v = ((const float4*)x)[j];
        float vv[4] = {v.x, v.y, v.z, v.w};
        __nv_bfloat16 h[4], l[4];
#pragma unroll
        for (int i = 0; i < 4; i++) {
            h[i] = __float2bfloat16(vv[i]);
            l[i] = __float2bfloat16(vv[i] - __bfloat162float(h[i]));
        }
        __nv_bfloat162 p0, p1, q0, q1;
        p0.x = h[0]; p0.y = h[1]; p1.x = h[2]; p1.y = h[3];
        q0.x = l[0]; q0.y = l[1]; q1.x = l[2]; q1.y = l[3];
        ((__nv_bfloat162*)g_xh)[2*j]     = p0;
        ((__nv_bfloat162*)g_xh)[2*j + 1] = p1;
        ((__nv_bfloat162*)g_xl)[2*j]     = q0;
        ((__nv_bfloat162*)g_xl)[2*j + 1] = q1;
    }
    for (int j = blockIdx.x * blockDim.x + threadIdx.x; j < nw; j += stride) {
        float4 v = ((const float4*)w)[j];
        float vv[4] = {v.x, v.y, v.z, v.w};
        __nv_bfloat16 h[4], l[4];
#pragma unroll
        for (int i = 0; i < 4; i++) {
            h[i] = __float2bfloat16(vv[i]);
            l[i] = __float2bfloat16(vv[i] - __bfloat162float(h[i]));
        }
        __nv_bfloat162 p0, p1, q0, q1;
        p0.x = h[0]; p0.y = h[1]; p1.x = h[2]; p1.y = h[3];
        q0.x = l[0]; q0.y = l[1]; q1.x = l[2]; q1.y = l[3];
        ((__nv_bfloat162*)g_wh)[2*j]     = p0;
        ((__nv_bfloat162*)g_wh)[2*j + 1] = p1;
        ((__nv_bfloat162*)g_wl)[2*j]     = q0;
        ((__nv_bfloat162*)g_wl)[2*j + 1] = q1;
    }
}

// ---------------------------------------------------------------------------
// Kernel A1: QKV GEMM, mma.sync bf16 split, cp.async double-buffered.
// 128x128 tile, BK=32, 8 warps (4M x 2N), warp tile 32x64.  (R4-proven form)
// Dynamic smem: 2 stages x 4 arrays x (128 rows x 80B) = 81920 B.
// ---------------------------------------------------------------------------
#define ASTRIDE 20               // ints per smem row (16 data + 4 pad)
#define ARR_B   10240            // bytes per array per stage
#define STG_B   40960            // bytes per stage
#define QKV_DSMEM 81920

__device__ __forceinline__ void mma_bf16(float* c, const int* a, const int* b) {
    asm volatile("mma.sync.aligned.m16n8k16.row.col.f32.bf16.bf16.f32 "
        "{%0,%1,%2,%3}, {%4,%5,%6,%7}, {%8,%9}, {%0,%1,%2,%3};"
        : "+f"(c[0]), "+f"(c[1]), "+f"(c[2]), "+f"(c[3])
        : "r"(a[0]), "r"(a[1]), "r"(a[2]), "r"(a[3]), "r"(b[0]), "r"(b[1]));
}

__global__ void __launch_bounds__(256) qkv_mma_kernel() {
    extern __shared__ char dyn[];
    uint32_t sbase;
    asm("{ .reg .u64 tmp; cvta.to.shared.u64 tmp, %1; cvt.u32.u64 %0, tmp; }"
        : "=r"(sbase) : "l"(dyn));
    const int t = threadIdx.x, lane = t & 31, wid = t >> 5;
    const int g = lane >> 2, tig = lane & 3;
    const int warpM = wid & 3, warpN = wid >> 2;
    const int o0 = blockIdx.x * 128, m0 = blockIdx.y * 128;

    float acc[2][8][4] = {};

#define PREFETCH(st, k0) do {                                                  \
    int _s = (st) * STG_B;                                                     \
    _Pragma("unroll")                                                          \
    for (int _c = 0; _c < 2; _c++) {                                           \
        int ch = t + _c * 256;                                                 \
        int row = ch >> 2, qi = ch & 3;                                        \
        uint32_t doff = (uint32_t)(row * 80 + qi * 16);                        \
        size_t ga = (size_t)(m0 + row) * C_ + (k0) + qi * 8;                   \
        size_t gb = (size_t)(o0 + row) * C_ + (k0) + qi * 8;                   \
        asm volatile("cp.async.cg.shared.global [%0], [%1], 16;"               \
                     :: "r"(sbase + _s + doff), "l"(g_xh + ga));               \
        asm volatile("cp.async.cg.shared.global [%0], [%1], 16;"               \
                     :: "r"(sbase + _s + ARR_B + doff), "l"(g_xl + ga));       \
        asm volatile("cp.async.cg.shared.global [%0], [%1], 16;"               \
                     :: "r"(sbase + _s + 2 * ARR_B + doff), "l"(g_wh + gb));   \
        asm volatile("cp.async.cg.shared.global [%0], [%1], 16;"               \
                     :: "r"(sbase + _s + 3 * ARR_B + doff), "l"(g_wl + gb));   \
    } } while (0)

    PREFETCH(0, 0);
    asm volatile("cp.async.commit_group;");

    for (int it = 0; it < 24; it++) {
        if (it + 1 < 24) {
            PREFETCH((it + 1) & 1, (it + 1) * 32);
            asm volatile("cp.async.commit_group;");
            asm volatile("cp.async.wait_group 1;");
        } else {
            asm volatile("cp.async.wait_group 0;");
        }
        __syncthreads();

        const int* pAh = (const int*)(dyn + (it & 1) * STG_B);
        const int* pAl = (const int*)(dyn + (it & 1) * STG_B + ARR_B);
        const int* pBh = (const int*)(dyn + (it & 1) * STG_B + 2 * ARR_B);
        const int* pBl = (const int*)(dyn + (it & 1) * STG_B + 3 * ARR_B);
#pragma unroll
        for (int ks = 0; ks < 2; ks++) {
            int ah[2][4], al[2][4];
#pragma unroll
            for (int mi = 0; mi < 2; mi++) {
                int r0 = (warpM * 32 + mi * 16 + g) * ASTRIDE + ks * 8 + tig;
                ah[mi][0] = pAh[r0];
                ah[mi][1] = pAh[r0 + 8 * ASTRIDE];
                ah[mi][2] = pAh[r0 + 4];
                ah[mi][3] = pAh[r0 + 8 * ASTRIDE + 4];
                al[mi][0] = pAl[r0];
                al[mi][1] = pAl[r0 + 8 * ASTRIDE];
                al[mi][2] = pAl[r0 + 4];
                al[mi][3] = pAl[r0 + 8 * ASTRIDE + 4];
            }
#pragma unroll
            for (int ni = 0; ni < 8; ni++) {
                int rb = (warpN * 64 + ni * 8 + g) * ASTRIDE + ks * 8 + tig;
                int bhf[2] = { pBh[rb], pBh[rb + 4] };
                int blf[2] = { pBl[rb], pBl[rb + 4] };
#pragma unroll
                for (int mi = 0; mi < 2; mi++) {
                    mma_bf16(acc[mi][ni], ah[mi], bhf);
                    mma_bf16(acc[mi][ni], ah[mi], blf);
                    mma_bf16(acc[mi][ni], al[mi], bhf);
                }
            }
        }
        __syncthreads();
    }

    // Epilogue: provisional spikes + warp-aggregated push of uncertain coords
    const int tt = o0 / 768;
    const int h0 = ((o0 % 768) >> 6) + warpN;
    const int bh = (m0 >> 10) * H_ + h0;
    const int nb = (m0 & 1023) + warpM * 32;
#pragma unroll
    for (int mi = 0; mi < 2; mi++) {
#pragma unroll
        for (int ni = 0; ni < 8; ni++) {
            int8_t sv[4];
#pragma unroll
            for (int e = 0; e < 4; e++) {
                float v = acc[mi][ni][e];
                sv[e] = (int8_t)spike_of(v);
                bool unc = (fabsf(v - 0.5f) < MARGIN) || (fabsf(v + 0.5f) < MARGIN);
                unsigned msk = __ballot_sync(0xffffffffu, unc);
                if (msk) {
                    int ldr = __ffs(msk) - 1;
                    int base = 0;
                    if (lane == ldr) base = atomicAdd(&g_nfix, __popc(msk));
                    base = __shfl_sync(0xffffffffu, base, ldr);
                    if (unc) {
                        int mg = m0 + warpM * 32 + mi * 16 + g + ((e >> 1) ? 8 : 0);
                        int og = o0 + warpN * 64 + ni * 8 + tig * 2 + (e & 1);
                        int pos = base + __popc(msk & ((1u << lane) - 1));
                        if (pos < FIXCAP) g_fix_list[pos] = mg * O3_ + og;
                    }
                }
            }
            int n1 = nb + mi * 16 + g;
            int d = ni * 8 + tig * 2;
            char2 v0, v1;
            v0.x = sv[0]; v0.y = sv[1];
            v1.x = sv[2]; v1.y = sv[3];
            *(char2*)&g_spk[tt][bh][n1][d]     = v0;
            *(char2*)&g_spk[tt][bh][n1 + 8][d] = v1;
        }
    }
}

// ---------------------------------------------------------------------------
// Kernel A2: fixup — exact fp32 warp-dots for listed uncertain elements.
// ---------------------------------------------------------------------------
__global__ void __launch_bounds__(256) fixup_kernel(const float* __restrict__ x,
                                                    const float* __restrict__ w) {
    const int lane = threadIdx.x & 31;
    const int gw = (blockIdx.x * blockDim.x + threadIdx.x) >> 5;
    const int nw = (gridDim.x * blockDim.x) >> 5;
    int nfix = g_nfix;
    if (nfix > FIXCAP) nfix = FIXCAP;

    for (int i = gw; i < nfix; i += nw) {
        int code = g_fix_list[i];
        int m = code / O3_;
        int o = code - m * O3_;
        const float4* xp = (const float4*)(x + (size_t)m * C_);
        const float4* wp = (const float4*)(w + (size_t)o * C_);
        float s = 0.0f;
#pragma unroll
        for (int c = 0; c < 6; c++) {
            float4 xv = xp[lane + c * 32];
            float4 wv = wp[lane + c * 32];
            s += xv.x * wv.x + xv.y * wv.y + xv.z * wv.z + xv.w * wv.w;
        }
#pragma unroll
        for (int off = 16; off; off >>= 1)
            s += __shfl_xor_sync(0xffffffffu, s, off);
        if (lane == 0) {
            int tt = o / 768, rem = o - tt * 768;
            g_spk[tt][(m >> 10) * H_ + (rem >> 6)][m & 1023][rem & 63] =
                (int8_t)spike_of(s);
        }
    }
}

// ---------------------------------------------------------------------------
// Kernel B: FUSED attention — s8 IMMA logits into smem, then per-row
// integer reject / rare exact softmax + v-row select.
// Dynamic smem: ssq 4KB @0, ssk 4KB @4096, sd 64 x 1040B @8192.
// ---------------------------------------------------------------------------
#define ATTN_DSMEM (8192 + 64 * 1040)

__global__ void __launch_bounds__(128) attn_kernel() {
    extern __shared__ char dyn[];
    char* ssq = dyn;
    char* ssk = dyn + 4096;
    char* sd  = dyn + 8192;
    const int t = threadIdx.x;
    const int lane = t & 31, wrp = t >> 5;
    const int gid = lane >> 2, tig = lane & 3;
    const int bh = blockIdx.y, n0 = blockIdx.x * 64;
    const int b = bh / H_, h = bh - b * H_;

    {
        const int4* src = (const int4*)&g_spk[0][bh][n0][0];
        int4* dst = (int4*)ssq;
        dst[t] = src[t]; dst[t + 128] = src[t + 128];
    }
    __syncthreads();

    int afr[2][4];
#pragma unroll
    for (int ks = 0; ks < 2; ks++) {
        int r = wrp * 16 + gid;
        afr[ks][0] = *(const int*)(ssq + r * 64 + ks * 32 + tig * 4);
        afr[ks][1] = *(const int*)(ssq + (r + 8) * 64 + ks * 32 + tig * 4);
        afr[ks][2] = *(const int*)(ssq + r * 64 + ks * 32 + 16 + tig * 4);
        afr[ks][3] = *(const int*)(ssq + (r + 8) * 64 + ks * 32 + 16 + tig * 4);
    }

    for (int mc = 0; mc < 16; mc++) {
        __syncthreads();
        {
            const int4* src = (const int4*)&g_spk[1][bh][mc * 64][0];
            int4* dst = (int4*)ssk;
            dst[t] = src[t]; dst[t + 128] = src[t + 128];
        }
        __syncthreads();
#pragma unroll
        for (int c = 0; c < 8; c++) {
            int c0 = 0, c1 = 0, c2 = 0, c3 = 0;
#pragma unroll
            for (int ks = 0; ks < 2; ks++) {
                int b0 = *(const int*)(ssk + (c * 8 + gid) * 64 + ks * 32 + tig * 4);
                int b1 = *(const int*)(ssk + (c * 8 + gid) * 64 + ks * 32 + 16 + tig * 4);
                asm volatile(
                    "mma.sync.aligned.m16n8k32.row.col.s32.s8.s8.s32 "
                    "{%0,%1,%2,%3}, {%4,%5,%6,%7}, {%8,%9}, {%0,%1,%2,%3};"
                    : "+r"(c0), "+r"(c1), "+r"(c2), "+r"(c3)
                    : "r"(afr[ks][0]), "r"(afr[ks][1]), "r"(afr[ks][2]), "r"(afr[ks][3]),
                      "r"(b0), "r"(b1));
            }
            int row = wrp * 16 + gid;
            int col = mc * 64 + c * 8 + tig * 2;
            char2 lo; lo.x = (char)c0; lo.y = (char)c1;
            char2 hi; hi.x = (char)c2; hi.y = (char)c3;
            *(char2*)(sd + row * 1040 + col)       = lo;
            *(char2*)(sd + (row + 8) * 1040 + col) = hi;
        }
    }
    __syncthreads();

    // Phase 2: each warp reduces 16 rows (integer reject; exact path is rare)
    for (int r = 0; r < 16; r++) {
        const int row = wrp * 16 + r;
        const char* rp = sd + row * 1040;
        int4 v0 = ((const int4*)rp)[lane];
        int4 v1 = ((const int4*)rp)[lane + 32];
        int words[8] = {v0.x, v0.y, v0.z, v0.w, v1.x, v1.y, v1.z, v1.w};

        // SIMD byte max
        int mxw = words[0];
#pragma unroll
        for (int wi = 1; wi < 8; wi++) mxw = __vmaxs4(mxw, words[wi]);
#pragma unroll
        for (int off = 16; off; off >>= 1)
            mxw = __vmaxs4(mxw, __shfl_xor_sync(0xffffffffu, mxw, off));
        int lmax = max(max((mxw << 24) >> 24, (mxw << 16) >> 24),
                       max((mxw << 8) >> 24,  mxw >> 24));

        // strong reject: count elements >= lmax - 24 (each contributes >= e^-3
        // to s). cnt >= 22 -> s >= 1 + 21*e^-3 = 2.0456 > 2 -> max softmax
        // prob <= 0.489 -> no spike possible. Fires for ~all rows.
        int t24 = lmax - 24;                       // lmax <= 64, so t24 >= -88 fits s8
        int tspl = (t24 & 0xff) * 0x01010101;
        int cnt = 0;
#pragma unroll
        for (int wi = 0; wi < 8; wi++)
            cnt += __popc(__vcmpges4(words[wi], tspl));
#pragma unroll
        for (int off = 16; off; off >>= 1)
            cnt += __shfl_xor_sync(0xffffffffu, cnt, off);

        int* dst = (int*)&g_s[b * N_ + n0 + row][h * D_];
        if (cnt >= 22 * 8) {    // popc counts 8 bits per passing byte
            if (lane < 16) dst[lane] = 0;
            continue;
        }

        // exact path (very rare): argmax + precise expf sum (reference math)
        float s = 0.0f;
        int larg = 0x7fffffff;
#pragma unroll
        for (int wi = 0; wi < 8; wi++) {
            int colbase = (wi < 4) ? (lane * 16 + wi * 4)
                                   : (512 + lane * 16 + (wi - 4) * 4);
#pragma unroll
            for (int j = 0; j < 4; j++) {
                int val = (words[wi] << (24 - 8 * j)) >> 24;
                s += expf(0.125f * (float)(val - lmax));
                if (val == lmax) larg = min(larg, colbase + j);
            }
        }
#pragma unroll
        for (int off = 16; off; off >>= 1) {
            s    += __shfl_xor_sync(0xffffffffu, s, off);
            larg  = min(larg, __shfl_xor_sync(0xffffffffu, larg, off));
        }
        float p = 1.0f / s;
        bool spk = (p + 0.5f) >= 1.0f;
        if (spk) {
            const int* src = (const int*)&g_spk[2][bh][larg][0];
            if (lane < 16) dst[lane] = src[lane];
            if (lane == 0) g_flag[b * N_ + n0 + row] = 1;
        } else {
            if (lane < 16) dst[lane] = 0;
        }
    }
}

// ---------------------------------------------------------------------------
// Kernel C: output projection (fp32 exact) + final IF, zero-tile skip.
// ---------------------------------------------------------------------------
__global__ void __launch_bounds__(256) proj_kernel(const float* __restrict__ wp,
                                                   float* __restrict__ out) {
    __shared__ float As[16][64];
    __shared__ float Bs[16][64];
    __shared__ int s_any;
    const int t = threadIdx.x;
    const int tx = t & 15, ty = t >> 4;
    const int m0 = blockIdx.y * 64, o0 = blockIdx.x * 64;
    const int lr = t >> 2, lc = (t & 3) * 4;

    if (t == 0) s_any = 0;
    __syncthreads();
    if (t < 64 && g_flag[m0 + t]) s_any = 1;
    __syncthreads();
    if (!s_any) {
        float4 z = make_float4(0.f, 0.f, 0.f, 0.f);
#pragma unroll
        for (int p = 0; p < 4; p++)
            *(float4*)&out[(size_t)(m0 + lr) * 768 + o0 + (t & 3) * 4 + p * 16] = z;
        return;
    }

    float acc[4][4] = {};
    for (int k0 = 0; k0 < 768; k0 += 16) {
        int    aw = *(const int*)&g_s[m0 + lr][k0 + lc];
        float4 bv = *(const float4*)&wp[(size_t)(o0 + lr) * 768 + k0 + lc];
        __syncthreads();
        As[lc + 0][lr] = (float)((aw << 24) >> 24);
        As[lc + 1][lr] = (float)((aw << 16) >> 24);
        As[lc + 2][lr] = (float)((aw << 8)  >> 24);
        As[lc + 3][lr] = (float)( aw        >> 24);
        Bs[lc + 0][lr] = bv.x; Bs[lc + 1][lr] = bv.y;
        Bs[lc + 2][lr] = bv.z; Bs[lc + 3][lr] = bv.w;
        __syncthreads();
#pragma unroll
        for (int k = 0; k < 16; k++) {
            float4 a = *(const float4*)&As[k][ty * 4];
            float4 b = *(const float4*)&Bs[k][tx * 4];
            float ar[4] = {a.x, a.y, a.z, a.w};
            float br[4] = {b.x, b.y, b.z, b.w};
#pragma unroll
            for (int i = 0; i < 4; i++)
#pragma unroll
                for (int j = 0; j < 4; j++)
                    acc[i][j] = fmaf(ar[i], br[j], acc[i][j]);
        }
    }
#pragma unroll
    for (int i = 0; i < 4; i++) {
        int m = m0 + ty * 4 + i;
#pragma unroll
        for (int j = 0; j < 4; j++) {
            int o = o0 + tx * 4 + j;
            out[(size_t)m * 768 + o] = (float)spike_of(acc[i][j]);
        }
    }
}

// ---------------------------------------------------------------------------
extern "C" void kernel_launch(void* const* d_in, const int* in_sizes, int n_in,
                              void* d_out, int out_size) {
    const float* x      = (const float*)d_in[0];
    const float* w_qkv  = (const float*)d_in[1];
    const float* w_proj = (const float*)d_in[2];
    float* out = (float*)d_out;

    cudaFuncSetAttribute(qkv_mma_kernel,
                         cudaFuncAttributeMaxDynamicSharedMemorySize, QKV_DSMEM);
    cudaFuncSetAttribute(attn_kernel,
                         cudaFuncAttributeMaxDynamicSharedMemorySize, ATTN_DSMEM);

    init_kernel<<<8, 1024>>>();
    convert_kernel<<<960, 256>>>(x, w_qkv);
    qkv_mma_kernel<<<dim3(18, 64), 256, QKV_DSMEM>>>();
    fixup_kernel<<<512, 256>>>(x, w_qkv);
    attn_kernel<<<dim3(16, 96), 128, ATTN_DSMEM>>>();
    proj_kernel<<<dim3(12, 128), 256>>>(w_proj, out);
}

// round 8
// speedup vs baseline: 1.2488x; 1.0216x over previous
#include <cuda_runtime.h>
#include <cuda_bf16.h>
#include <cstdint>

#define B_   8
#define N_   1024
#define C_   768
#define H_   12
#define D_   64
#define BH_  96
#define M_   8192
#define O3_  2304
#define FIXCAP (1 << 21)

// Scratch (static __device__ — no allocation in kernel_launch)
__device__ __align__(16) int8_t g_spk[3][BH_][N_][D_];   // q/k/v ternary spikes
__device__ __align__(16) int8_t g_s[M_][C_];             // post-attention spikes
__device__ int    g_flag[M_];                            // per-row spike flag
__device__ int    g_nfix;                                // uncertain-element count
__device__ int    g_fix_list[FIXCAP];                    // packed m*2304+o
__device__ __align__(16) __nv_bfloat16 g_xh[M_ * C_];    // x split hi
__device__ __align__(16) __nv_bfloat16 g_xl[M_ * C_];    // x split lo
__device__ __align__(16) __nv_bfloat16 g_wh[O3_ * C_];   // w_qkv split hi
__device__ __align__(16) __nv_bfloat16 g_wl[O3_ * C_];   // w_qkv split lo

#define MARGIN 4e-4f

__device__ __forceinline__ int spike_of(float v) {
    float u = v + 0.5f;                        // replicate reference op order
    return (u >= 1.0f) ? 1 : ((u < 0.0f) ? -1 : 0);
}

// ---------------------------------------------------------------------------
// Kernel 0: zero flags + fixup counter (graph replays need deterministic init)
// ---------------------------------------------------------------------------
__global__ void init_kernel() {
    int i = blockIdx.x * blockDim.x + threadIdx.x;
    if (i < M_) g_flag[i] = 0;
    if (i == 0) g_nfix = 0;
}

// ---------------------------------------------------------------------------
// Kernel A0: fp32 -> bf16 hi/lo split of x and w_qkv.
// ---------------------------------------------------------------------------
__global__ void __launch_bounds__(256) convert_kernel(const float* __restrict__ x,
                                                      const float* __restrict__ w) {
    const int stride = gridDim.x * blockDim.x;
    const int nx = M_ * C_ / 4, nw = O3_ * C_ / 4;
    for (int j = blockIdx.x * blockDim.x + threadIdx.x; j < nx; j += stride) {
        float4 v = ((const float4*)x)[j];
        float vv[4] = {v.x, v.y, v.z, v.w};
        __nv_bfloat16 h[4], l[4];
#pragma unroll
        for (int i = 0; i < 4; i++) {
            h[i] = __float2bfloat16(vv[i]);
            l[i] = __float2bfloat16(vv[i] - __bfloat162float(h[i]));
        }
        __nv_bfloat162 p0, p1, q0, q1;
        p0.x = h[0]; p0.y = h[1]; p1.x = h[2]; p1.y = h[3];
        q0.x = l[0]; q0.y = l[1]; q1.x = l[2]; q1.y = l[3];
        ((__nv_bfloat162*)g_xh)[2*j]     = p0;
        ((__nv_bfloat162*)g_xh)[2*j + 1] = p1;
        ((__nv_bfloat162*)g_xl)[2*j]     = q0;
        ((__nv_bfloat162*)g_xl)[2*j + 1] = q1;
    }
    for (int j = blockIdx.x * blockDim.x + threadIdx.x; j < nw; j += stride) {
        float4 v = ((const float4*)w)[j];
        float vv[4] = {v.x, v.y, v.z, v.w};
        __nv_bfloat16 h[4], l[4];
#pragma unroll
        for (int i = 0; i < 4; i++) {
            h[i] = __float2bfloat16(vv[i]);
            l[i] = __float2bfloat16(vv[i] - __bfloat162float(h[i]));
        }
        __nv_bfloat162 p0, p1, q0, q1;
        p0.x = h[0]; p0.y = h[1]; p1.x = h[2]; p1.y = h[3];
        q0.x = l[0]; q0.y = l[1]; q1.x = l[2]; q1.y = l[3];
        ((__nv_bfloat162*)g_wh)[2*j]     = p0;
        ((__nv_bfloat162*)g_wh)[2*j + 1] = p1;
        ((__nv_bfloat162*)g_wl)[2*j]     = q0;
        ((__nv_bfloat162*)g_wl)[2*j + 1] = q1;
    }
}

// ---------------------------------------------------------------------------
// Kernel A1: QKV GEMM, mma.sync bf16 split, cp.async double-buffered.
// 128x128 tile, BK=32, 8 warps (4M x 2N), warp tile 32x64.  (R4-proven form)
// Dynamic smem: 2 stages x 4 arrays x (128 rows x 80B) = 81920 B.
// ---------------------------------------------------------------------------
#define ASTRIDE 20               // ints per smem row (16 data + 4 pad)
#define ARR_B   10240            // bytes per array per stage
#define STG_B   40960            // bytes per stage
#define QKV_DSMEM 81920

__device__ __forceinline__ void mma_bf16(float* c, const int* a, const int* b) {
    asm volatile("mma.sync.aligned.m16n8k16.row.col.f32.bf16.bf16.f32 "
        "{%0,%1,%2,%3}, {%4,%5,%6,%7}, {%8,%9}, {%0,%1,%2,%3};"
        : "+f"(c[0]), "+f"(c[1]), "+f"(c[2]), "+f"(c[3])
        : "r"(a[0]), "r"(a[1]), "r"(a[2]), "r"(a[3]), "r"(b[0]), "r"(b[1]));
}

__global__ void __launch_bounds__(256) qkv_mma_kernel() {
    extern __shared__ char dyn[];
    uint32_t sbase;
    asm("{ .reg .u64 tmp; cvta.to.shared.u64 tmp, %1; cvt.u32.u64 %0, tmp; }"
        : "=r"(sbase) : "l"(dyn));
    const int t = threadIdx.x, lane = t & 31, wid = t >> 5;
    const int g = lane >> 2, tig = lane & 3;
    const int warpM = wid & 3, warpN = wid >> 2;
    const int o0 = blockIdx.x * 128, m0 = blockIdx.y * 128;

    float acc[2][8][4] = {};

#define PREFETCH(st, k0) do {                                                  \
    int _s = (st) * STG_B;                                                     \
    _Pragma("unroll")                                                          \
    for (int _c = 0; _c < 2; _c++) {                                           \
        int ch = t + _c * 256;                                                 \
        int row = ch >> 2, qi = ch & 3;                                        \
        uint32_t doff = (uint32_t)(row * 80 + qi * 16);                        \
        size_t ga = (size_t)(m0 + row) * C_ + (k0) + qi * 8;                   \
        size_t gb = (size_t)(o0 + row) * C_ + (k0) + qi * 8;                   \
        asm volatile("cp.async.cg.shared.global [%0], [%1], 16;"               \
                     :: "r"(sbase + _s + doff), "l"(g_xh + ga));               \
        asm volatile("cp.async.cg.shared.global [%0], [%1], 16;"               \
                     :: "r"(sbase + _s + ARR_B + doff), "l"(g_xl + ga));       \
        asm volatile("cp.async.cg.shared.global [%0], [%1], 16;"               \
                     :: "r"(sbase + _s + 2 * ARR_B + doff), "l"(g_wh + gb));   \
        asm volatile("cp.async.cg.shared.global [%0], [%1], 16;"               \
                     :: "r"(sbase + _s + 3 * ARR_B + doff), "l"(g_wl + gb));   \
    } } while (0)

    PREFETCH(0, 0);
    asm volatile("cp.async.commit_group;");

    for (int it = 0; it < 24; it++) {
        if (it + 1 < 24) {
            PREFETCH((it + 1) & 1, (it + 1) * 32);
            asm volatile("cp.async.commit_group;");
            asm volatile("cp.async.wait_group 1;");
        } else {
            asm volatile("cp.async.wait_group 0;");
        }
        __syncthreads();

        const int* pAh = (const int*)(dyn + (it & 1) * STG_B);
        const int* pAl = (const int*)(dyn + (it & 1) * STG_B + ARR_B);
        const int* pBh = (const int*)(dyn + (it & 1) * STG_B + 2 * ARR_B);
        const int* pBl = (const int*)(dyn + (it & 1) * STG_B + 3 * ARR_B);
#pragma unroll
        for (int ks = 0; ks < 2; ks++) {
            int ah[2][4], al[2][4];
#pragma unroll
            for (int mi = 0; mi < 2; mi++) {
                int r0 = (warpM * 32 + mi * 16 + g) * ASTRIDE + ks * 8 + tig;
                ah[mi][0] = pAh[r0];
                ah[mi][1] = pAh[r0 + 8 * ASTRIDE];
                ah[mi][2] = pAh[r0 + 4];
                ah[mi][3] = pAh[r0 + 8 * ASTRIDE + 4];
                al[mi][0] = pAl[r0];
                al[mi][1] = pAl[r0 + 8 * ASTRIDE];
                al[mi][2] = pAl[r0 + 4];
                al[mi][3] = pAl[r0 + 8 * ASTRIDE + 4];
            }
#pragma unroll
            for (int ni = 0; ni < 8; ni++) {
                int rb = (warpN * 64 + ni * 8 + g) * ASTRIDE + ks * 8 + tig;
                int bhf[2] = { pBh[rb], pBh[rb + 4] };
                int blf[2] = { pBl[rb], pBl[rb + 4] };
#pragma unroll
                for (int mi = 0; mi < 2; mi++) {
                    mma_bf16(acc[mi][ni], ah[mi], bhf);
                    mma_bf16(acc[mi][ni], ah[mi], blf);
                    mma_bf16(acc[mi][ni], al[mi], bhf);
                }
            }
        }
        __syncthreads();
    }

    // Epilogue: provisional spikes + warp-aggregated push of uncertain coords
    const int tt = o0 / 768;
    const int h0 = ((o0 % 768) >> 6) + warpN;
    const int bh = (m0 >> 10) * H_ + h0;
    const int nb = (m0 & 1023) + warpM * 32;
#pragma unroll
    for (int mi = 0; mi < 2; mi++) {
#pragma unroll
        for (int ni = 0; ni < 8; ni++) {
            int8_t sv[4];
#pragma unroll
            for (int e = 0; e < 4; e++) {
                float v = acc[mi][ni][e];
                sv[e] = (int8_t)spike_of(v);
                bool unc = (fabsf(v - 0.5f) < MARGIN) || (fabsf(v + 0.5f) < MARGIN);
                unsigned msk = __ballot_sync(0xffffffffu, unc);
                if (msk) {
                    int ldr = __ffs(msk) - 1;
                    int base = 0;
                    if (lane == ldr) base = atomicAdd(&g_nfix, __popc(msk));
                    base = __shfl_sync(0xffffffffu, base, ldr);
                    if (unc) {
                        int mg = m0 + warpM * 32 + mi * 16 + g + ((e >> 1) ? 8 : 0);
                        int og = o0 + warpN * 64 + ni * 8 + tig * 2 + (e & 1);
                        int pos = base + __popc(msk & ((1u << lane) - 1));
                        if (pos < FIXCAP) g_fix_list[pos] = mg * O3_ + og;
                    }
                }
            }
            int n1 = nb + mi * 16 + g;
            int d = ni * 8 + tig * 2;
            char2 v0, v1;
            v0.x = sv[0]; v0.y = sv[1];
            v1.x = sv[2]; v1.y = sv[3];
            *(char2*)&g_spk[tt][bh][n1][d]     = v0;
            *(char2*)&g_spk[tt][bh][n1 + 8][d] = v1;
        }
    }
}

// ---------------------------------------------------------------------------
// Kernel A2: fixup — exact fp32 warp-dots for listed uncertain elements.
// ---------------------------------------------------------------------------
__global__ void __launch_bounds__(256) fixup_kernel(const float* __restrict__ x,
                                                    const float* __restrict__ w) {
    const int lane = threadIdx.x & 31;
    const int gw = (blockIdx.x * blockDim.x + threadIdx.x) >> 5;
    const int nw = (gridDim.x * blockDim.x) >> 5;
    int nfix = g_nfix;
    if (nfix > FIXCAP) nfix = FIXCAP;

    for (int i = gw; i < nfix; i += nw) {
        int code = g_fix_list[i];
        int m = code / O3_;
        int o = code - m * O3_;
        const float4* xp = (const float4*)(x + (size_t)m * C_);
        const float4* wp = (const float4*)(w + (size_t)o * C_);
        float s = 0.0f;
#pragma unroll
        for (int c = 0; c < 6; c++) {
            float4 xv = xp[lane + c * 32];
            float4 wv = wp[lane + c * 32];
            s += xv.x * wv.x + xv.y * wv.y + xv.z * wv.z + xv.w * wv.w;
        }
#pragma unroll
        for (int off = 16; off; off >>= 1)
            s += __shfl_xor_sync(0xffffffffu, s, off);
        if (lane == 0) {
            int tt = o / 768, rem = o - tt * 768;
            g_spk[tt][(m >> 10) * H_ + (rem >> 6)][m & 1023][rem & 63] =
                (int8_t)spike_of(s);
        }
    }
}

// ---------------------------------------------------------------------------
// Kernel B: FUSED attention, 8 warps. Two 4-warp groups split the 16
// K-chunks (group g handles mc = g*8 .. g*8+7) with private ssk buffers,
// halving the serialized MMA phase. Then 8-warp row reduction.
// Dynamic smem: ssq 4KB @0, ssk[2] 4KB @4096/@8192, sd 64 x 1040B @12288.
// ---------------------------------------------------------------------------
#define ATTN_DSMEM (12288 + 64 * 1040)

__global__ void __launch_bounds__(256) attn_kernel() {
    extern __shared__ char dyn[];
    char* ssq = dyn;
    char* sd  = dyn + 12288;
    const int t = threadIdx.x;
    const int lane = t & 31, wid = t >> 5;
    const int wg = t >> 7;            // warp group 0/1
    const int tg = t & 127;           // thread-in-group
    const int wrp2 = (t >> 5) & 3;    // warp-in-group
    const int gid = lane >> 2, tig = lane & 3;
    const int bh = blockIdx.y, n0 = blockIdx.x * 64;
    const int b = bh / H_, h = bh - b * H_;

    {   // ssq: 4KB loaded by all 256 threads
        const int4* src = (const int4*)&g_spk[0][bh][n0][0];
        ((int4*)ssq)[t] = src[t];
    }
    __syncthreads();

    int afr[2][4];
#pragma unroll
    for (int ks = 0; ks < 2; ks++) {
        int r = wrp2 * 16 + gid;
        afr[ks][0] = *(const int*)(ssq + r * 64 + ks * 32 + tig * 4);
        afr[ks][1] = *(const int*)(ssq + (r + 8) * 64 + ks * 32 + tig * 4);
        afr[ks][2] = *(const int*)(ssq + r * 64 + ks * 32 + 16 + tig * 4);
        afr[ks][3] = *(const int*)(ssq + (r + 8) * 64 + ks * 32 + 16 + tig * 4);
    }

    char* ssk = dyn + 4096 + wg * 4096;
    for (int i = 0; i < 8; i++) {
        const int mc = wg * 8 + i;
        __syncthreads();
        {   // each group loads its own 4KB K tile
            const int4* src = (const int4*)&g_spk[1][bh][mc * 64][0];
            int4* dst = (int4*)ssk;
            dst[tg] = src[tg]; dst[tg + 128] = src[tg + 128];
        }
        __syncthreads();
#pragma unroll
        for (int c = 0; c < 8; c++) {
            int c0 = 0, c1 = 0, c2 = 0, c3 = 0;
#pragma unroll
            for (int ks = 0; ks < 2; ks++) {
                int b0 = *(const int*)(ssk + (c * 8 + gid) * 64 + ks * 32 + tig * 4);
                int b1 = *(const int*)(ssk + (c * 8 + gid) * 64 + ks * 32 + 16 + tig * 4);
                asm volatile(
                    "mma.sync.aligned.m16n8k32.row.col.s32.s8.s8.s32 "
                    "{%0,%1,%2,%3}, {%4,%5,%6,%7}, {%8,%9}, {%0,%1,%2,%3};"
                    : "+r"(c0), "+r"(c1), "+r"(c2), "+r"(c3)
                    : "r"(afr[ks][0]), "r"(afr[ks][1]), "r"(afr[ks][2]), "r"(afr[ks][3]),
                      "r"(b0), "r"(b1));
            }
            int row = wrp2 * 16 + gid;
            int col = mc * 64 + c * 8 + tig * 2;
            char2 lo; lo.x = (char)c0; lo.y = (char)c1;
            char2 hi; hi.x = (char)c2; hi.y = (char)c3;
            *(char2*)(sd + row * 1040 + col)       = lo;
            *(char2*)(sd + (row + 8) * 1040 + col) = hi;
        }
    }
    __syncthreads();

    // Phase 2: 8 warps x 8 rows (integer reject; exact path is rare)
    for (int r = 0; r < 8; r++) {
        const int row = wid * 8 + r;
        const char* rp = sd + row * 1040;
        int4 v0 = ((const int4*)rp)[lane];
        int4 v1 = ((const int4*)rp)[lane + 32];
        int words[8] = {v0.x, v0.y, v0.z, v0.w, v1.x, v1.y, v1.z, v1.w};

        // SIMD byte max
        int mxw = words[0];
#pragma unroll
        for (int wi = 1; wi < 8; wi++) mxw = __vmaxs4(mxw, words[wi]);
#pragma unroll
        for (int off = 16; off; off >>= 1)
            mxw = __vmaxs4(mxw, __shfl_xor_sync(0xffffffffu, mxw, off));
        int lmax = max(max((mxw << 24) >> 24, (mxw << 16) >> 24),
                       max((mxw << 8) >> 24,  mxw >> 24));

        // strong reject: count elements >= lmax - 24 (each contributes >= e^-3
        // to s). cnt >= 22 -> s >= 1 + 21*e^-3 = 2.0456 > 2 -> max softmax
        // prob <= 0.489 -> no spike possible. Fires for ~all rows.
        int t24 = lmax - 24;
        int tspl = (t24 & 0xff) * 0x01010101;
        int cnt = 0;
#pragma unroll
        for (int wi = 0; wi < 8; wi++)
            cnt += __popc(__vcmpges4(words[wi], tspl));
#pragma unroll
        for (int off = 16; off; off >>= 1)
            cnt += __shfl_xor_sync(0xffffffffu, cnt, off);

        int* dst = (int*)&g_s[b * N_ + n0 + row][h * D_];
        if (cnt >= 22 * 8) {    // popc counts 8 bits per passing byte
            if (lane < 16) dst[lane] = 0;
            continue;
        }

        // exact path (very rare): argmax + precise expf sum (reference math)
        float s = 0.0f;
        int larg = 0x7fffffff;
#pragma unroll
        for (int wi = 0; wi < 8; wi++) {
            int colbase = (wi < 4) ? (lane * 16 + wi * 4)
                                   : (512 + lane * 16 + (wi - 4) * 4);
#pragma unroll
            for (int j = 0; j < 4; j++) {
                int val = (words[wi] << (24 - 8 * j)) >> 24;
                s += expf(0.125f * (float)(val - lmax));
                if (val == lmax) larg = min(larg, colbase + j);
            }
        }
#pragma unroll
        for (int off = 16; off; off >>= 1) {
            s    += __shfl_xor_sync(0xffffffffu, s, off);
            larg  = min(larg, __shfl_xor_sync(0xffffffffu, larg, off));
        }
        float p = 1.0f / s;
        bool spk = (p + 0.5f) >= 1.0f;
        if (spk) {
            const int* src = (const int*)&g_spk[2][bh][larg][0];
            if (lane < 16) dst[lane] = src[lane];
            if (lane == 0) g_flag[b * N_ + n0 + row] = 1;
        } else {
            if (lane < 16) dst[lane] = 0;
        }
    }
}

// ---------------------------------------------------------------------------
// Kernel C: output projection (fp32 exact) + final IF, zero-tile skip.
// ---------------------------------------------------------------------------
__global__ void __launch_bounds__(256) proj_kernel(const float* __restrict__ wp,
                                                   float* __restrict__ out) {
    __shared__ float As[16][64];
    __shared__ float Bs[16][64];
    __shared__ int s_any;
    const int t = threadIdx.x;
    const int tx = t & 15, ty = t >> 4;
    const int m0 = blockIdx.y * 64, o0 = blockIdx.x * 64;
    const int lr = t >> 2, lc = (t & 3) * 4;

    if (t == 0) s_any = 0;
    __syncthreads();
    if (t < 64 && g_flag[m0 + t]) s_any = 1;
    __syncthreads();
    if (!s_any) {
        float4 z = make_float4(0.f, 0.f, 0.f, 0.f);
#pragma unroll
        for (int p = 0; p < 4; p++)
            *(float4*)&out[(size_t)(m0 + lr) * 768 + o0 + (t & 3) * 4 + p * 16] = z;
        return;
    }

    float acc[4][4] = {};
    for (int k0 = 0; k0 < 768; k0 += 16) {
        int    aw = *(const int*)&g_s[m0 + lr][k0 + lc];
        float4 bv = *(const float4*)&wp[(size_t)(o0 + lr) * 768 + k0 + lc];
        __syncthreads();
        As[lc + 0][lr] = (float)((aw << 24) >> 24);
        As[lc + 1][lr] = (float)((aw << 16) >> 24);
        As[lc + 2][lr] = (float)((aw << 8)  >> 24);
        As[lc + 3][lr] = (float)( aw        >> 24);
        Bs[lc + 0][lr] = bv.x; Bs[lc + 1][lr] = bv.y;
        Bs[lc + 2][lr] = bv.z; Bs[lc + 3][lr] = bv.w;
        __syncthreads();
#pragma unroll
        for (int k = 0; k < 16; k++) {
            float4 a = *(const float4*)&As[k][ty * 4];
            float4 b = *(const float4*)&Bs[k][tx * 4];
            float ar[4] = {a.x, a.y, a.z, a.w};
            float br[4] = {b.x, b.y, b.z, b.w};
#pragma unroll
            for (int i = 0; i < 4; i++)
#pragma unroll
                for (int j = 0; j < 4; j++)
                    acc[i][j] = fmaf(ar[i], br[j], acc[i][j]);
        }
    }
#pragma unroll
    for (int i = 0; i < 4; i++) {
        int m = m0 + ty * 4 + i;
#pragma unroll
        for (int j = 0; j < 4; j++) {
            int o = o0 + tx * 4 + j;
            out[(size_t)m * 768 + o] = (float)spike_of(acc[i][j]);
        }
    }
}

// ---------------------------------------------------------------------------
extern "C" void kernel_launch(void* const* d_in, const int* in_sizes, int n_in,
                              void* d_out, int out_size) {
    const float* x      = (const float*)d_in[0];
    const float* w_qkv  = (const float*)d_in[1];
    const float* w_proj = (const float*)d_in[2];
    float* out = (float*)d_out;

    cudaFuncSetAttribute(qkv_mma_kernel,
                         cudaFuncAttributeMaxDynamicSharedMemorySize, QKV_DSMEM);
    cudaFuncSetAttribute(attn_kernel,
                         cudaFuncAttributeMaxDynamicSharedMemorySize, ATTN_DSMEM);

    init_kernel<<<8, 1024>>>();
    convert_kernel<<<960, 256>>>(x, w_qkv);
    qkv_mma_kernel<<<dim3(18, 64), 256, QKV_DSMEM>>>();
    fixup_kernel<<<512, 256>>>(x, w_qkv);
    attn_kernel<<<dim3(16, 96), 256, ATTN_DSMEM>>>();
    proj_kernel<<<dim3(12, 128), 256>>>(w_proj, out);
}

// round 9
// speedup vs baseline: 1.3354x; 1.0693x over previous
#include <cuda_runtime.h>
#include <cuda_bf16.h>
#include <cstdint>

#define B_   8
#define N_   1024
#define C_   768
#define H_   12
#define D_   64
#define BH_  96
#define M_   8192
#define O3_  2304
#define FIXCAP (1 << 21)

// Scratch (static __device__ — no allocation in kernel_launch)
__device__ __align__(16) int8_t g_spk[3][BH_][N_][D_];   // q/k/v ternary spikes
__device__ __align__(16) int8_t g_s[M_][C_];             // post-attention spikes
__device__ int    g_flag[M_];                            // per-row spike flag
__device__ int    g_nfix;                                // uncertain-element count
__device__ int    g_fix_list[FIXCAP];                    // packed m*2304+o
__device__ __align__(16) __nv_bfloat16 g_xh[M_ * C_];    // x split hi
__device__ __align__(16) __nv_bfloat16 g_xl[M_ * C_];    // x split lo
// w_qkv hi/lo planes in MMA-fragment-permuted layout:
//   [o_grp 288][k_grp 48][256B tile]; tile: lane*8 + breg*4 + (k&1)*2
__device__ __align__(16) int8_t g_whp[288 * 48 * 256];
__device__ __align__(16) int8_t g_wlp[288 * 48 * 256];

#define MARGIN 4e-4f

__device__ __forceinline__ int spike_of(float v) {
    float u = v + 0.5f;                        // replicate reference op order
    return (u >= 1.0f) ? 1 : ((u < 0.0f) ? -1 : 0);
}

// ---------------------------------------------------------------------------
// Kernel 1: fp32 -> bf16 hi/lo split of x (row-major, unchanged layout).
// ---------------------------------------------------------------------------
__global__ void __launch_bounds__(256) convert_x_kernel(const float* __restrict__ x) {
    const int stride = gridDim.x * blockDim.x;
    const int nx = M_ * C_ / 4;
    for (int j = blockIdx.x * blockDim.x + threadIdx.x; j < nx; j += stride) {
        float4 v = ((const float4*)x)[j];
        float vv[4] = {v.x, v.y, v.z, v.w};
        __nv_bfloat16 h[4], l[4];
#pragma unroll
        for (int i = 0; i < 4; i++) {
            h[i] = __float2bfloat16(vv[i]);
            l[i] = __float2bfloat16(vv[i] - __bfloat162float(h[i]));
        }
        __nv_bfloat162 p0, p1, q0, q1;
        p0.x = h[0]; p0.y = h[1]; p1.x = h[2]; p1.y = h[3];
        q0.x = l[0]; q0.y = l[1]; q1.x = l[2]; q1.y = l[3];
        ((__nv_bfloat162*)g_xh)[2*j]     = p0;
        ((__nv_bfloat162*)g_xh)[2*j + 1] = p1;
        ((__nv_bfloat162*)g_xl)[2*j]     = q0;
        ((__nv_bfloat162*)g_xl)[2*j + 1] = q1;
    }
}

// ---------------------------------------------------------------------------
// Kernel 2: fp32 -> bf16 hi/lo split of w_qkv, permuted to MMA B-fragment
// layout. For (o, c): tile (o>>3, c>>4); lane = (o&7)*4 + ((c&7)>>1);
// breg = (c>>3)&1; byte = (c&1)*2. Pairs (c, c+1) share one 4B word.
// ---------------------------------------------------------------------------
__global__ void __launch_bounds__(256) convert_w_kernel(const float* __restrict__ w) {
    const int stride = gridDim.x * blockDim.x;
    const int np = O3_ * C_ / 2;
    for (int j = blockIdx.x * blockDim.x + threadIdx.x; j < np; j += stride) {
        int o = (2 * j) / C_;
        int c = (2 * j) % C_;
        float2 v = *(const float2*)(w + (size_t)o * C_ + c);
        __nv_bfloat16 h0 = __float2bfloat16(v.x);
        __nv_bfloat16 l0 = __float2bfloat16(v.x - __bfloat162float(h0));
        __nv_bfloat16 h1 = __float2bfloat16(v.y);
        __nv_bfloat16 l1 = __float2bfloat16(v.y - __bfloat162float(h1));
        int kgrp = c >> 4, kin = c & 15;
        int lanep = ((o & 7) << 2) | ((kin & 7) >> 1);
        int breg  = kin >> 3;
        size_t dst = (size_t)(o >> 3) * 12288 + (size_t)kgrp * 256
                   + lanep * 8 + breg * 4;
        __nv_bfloat162 hp; hp.x = h0; hp.y = h1;
        __nv_bfloat162 lp; lp.x = l0; lp.y = l1;
        *(__nv_bfloat162*)(g_whp + dst) = hp;
        *(__nv_bfloat162*)(g_wlp + dst) = lp;
    }
}

// ---------------------------------------------------------------------------
// Kernel 3: zero flags + fixup counter (deterministic across graph replays)
// ---------------------------------------------------------------------------
__global__ void init_kernel() {
    int i = blockIdx.x * blockDim.x + threadIdx.x;
    if (i < M_) g_flag[i] = 0;
    if (i == 0) g_nfix = 0;
}

// ---------------------------------------------------------------------------
// Kernel 4 (ncu-profiled slot): QKV GEMM, mma.sync bf16 split (hh+hl+lh),
// cp.async double-buffered. 128x128 tile, BK=32, 8 warps, warp tile 32x64.
// Smem per stage: Ah 10240 | Al 10240 | Bh 8192 | Bl 8192 = 36864; 2 stages.
// B planes are fragment-contiguous: one LDS.64 per (ni, ks) fragment.
// ---------------------------------------------------------------------------
#define ASTRIDE 20               // ints per A smem row (16 data + 4 pad)
#define A_PL    10240
#define B_PL    8192
#define STG_B   36864
#define QKV_DSMEM 73728

__device__ __forceinline__ void mma_bf16(float* c, const int* a, const int* b) {
    asm volatile("mma.sync.aligned.m16n8k16.row.col.f32.bf16.bf16.f32 "
        "{%0,%1,%2,%3}, {%4,%5,%6,%7}, {%8,%9}, {%0,%1,%2,%3};"
        : "+f"(c[0]), "+f"(c[1]), "+f"(c[2]), "+f"(c[3])
        : "r"(a[0]), "r"(a[1]), "r"(a[2]), "r"(a[3]), "r"(b[0]), "r"(b[1]));
}

__global__ void __launch_bounds__(256) qkv_mma_kernel() {
    extern __shared__ char dyn[];
    uint32_t sbase;
    asm("{ .reg .u64 tmp; cvta.to.shared.u64 tmp, %1; cvt.u32.u64 %0, tmp; }"
        : "=r"(sbase) : "l"(dyn));
    const int t = threadIdx.x, lane = t & 31, wid = t >> 5;
    const int g = lane >> 2, tig = lane & 3;
    const int warpM = wid & 3, warpN = wid >> 2;
    const int o0 = blockIdx.x * 128, m0 = blockIdx.y * 128;

    float acc[2][8][4] = {};

#define PREFETCH(st, it) do {                                                  \
    int _s = (st) * STG_B;                                                     \
    _Pragma("unroll")                                                          \
    for (int _c = 0; _c < 2; _c++) {                                           \
        int ch = t + _c * 256;                                                 \
        int row = ch >> 2, qi = ch & 3;                                        \
        uint32_t doff = (uint32_t)(row * 80 + qi * 16);                        \
        size_t ga = (size_t)(m0 + row) * C_ + (it) * 32 + qi * 8;              \
        asm volatile("cp.async.cg.shared.global [%0], [%1], 16;"               \
                     :: "r"(sbase + _s + doff), "l"(g_xh + ga));               \
        asm volatile("cp.async.cg.shared.global [%0], [%1], 16;"               \
                     :: "r"(sbase + _s + A_PL + doff), "l"(g_xl + ga));        \
        int ogr = ch >> 5, woff = (ch & 31) * 16;                              \
        size_t gb = (size_t)((o0 >> 3) + ogr) * 12288 + (it) * 512 + woff;     \
        uint32_t bdst = (uint32_t)(ogr * 512 + woff);                          \
        asm volatile("cp.async.cg.shared.global [%0], [%1], 16;"               \
                     :: "r"(sbase + _s + 2 * A_PL + bdst), "l"(g_whp + gb));   \
        asm volatile("cp.async.cg.shared.global [%0], [%1], 16;"               \
                     :: "r"(sbase + _s + 2 * A_PL + B_PL + bdst),              \
                        "l"(g_wlp + gb));                                      \
    } } while (0)

    PREFETCH(0, 0);
    asm volatile("cp.async.commit_group;");

    for (int it = 0; it < 24; it++) {
        if (it + 1 < 24) {
            PREFETCH((it + 1) & 1, it + 1);
            asm volatile("cp.async.commit_group;");
            asm volatile("cp.async.wait_group 1;");
        } else {
            asm volatile("cp.async.wait_group 0;");
        }
        __syncthreads();

        const char* stg = dyn + (it & 1) * STG_B;
        const int* pAh = (const int*)stg;
        const int* pAl = (const int*)(stg + A_PL);
        const char* pBh = stg + 2 * A_PL;
        const char* pBl = stg + 2 * A_PL + B_PL;
#pragma unroll
        for (int ks = 0; ks < 2; ks++) {
            int ah[2][4], al[2][4];
#pragma unroll
            for (int mi = 0; mi < 2; mi++) {
                int r0 = (warpM * 32 + mi * 16 + g) * ASTRIDE + ks * 8 + tig;
                ah[mi][0] = pAh[r0];
                ah[mi][1] = pAh[r0 + 8 * ASTRIDE];
                ah[mi][2] = pAh[r0 + 4];
                ah[mi][3] = pAh[r0 + 8 * ASTRIDE + 4];
                al[mi][0] = pAl[r0];
                al[mi][1] = pAl[r0 + 8 * ASTRIDE];
                al[mi][2] = pAl[r0 + 4];
                al[mi][3] = pAl[r0 + 8 * ASTRIDE + 4];
            }
#pragma unroll
            for (int ni = 0; ni < 8; ni++) {
                int boff = (warpN * 8 + ni) * 512 + ks * 256 + lane * 8;
                int2 bh2 = *(const int2*)(pBh + boff);
                int2 bl2 = *(const int2*)(pBl + boff);
                int bhf[2] = { bh2.x, bh2.y };
                int blf[2] = { bl2.x, bl2.y };
#pragma unroll
                for (int mi = 0; mi < 2; mi++) {
                    mma_bf16(acc[mi][ni], ah[mi], bhf);
                    mma_bf16(acc[mi][ni], ah[mi], blf);
                    mma_bf16(acc[mi][ni], al[mi], bhf);
                }
            }
        }
        __syncthreads();
    }

    // Epilogue: provisional spikes + warp-aggregated push of uncertain coords
    const int tt = o0 / 768;
    const int h0 = ((o0 % 768) >> 6) + warpN;
    const int bh = (m0 >> 10) * H_ + h0;
    const int nb = (m0 & 1023) + warpM * 32;
#pragma unroll
    for (int mi = 0; mi < 2; mi++) {
#pragma unroll
        for (int ni = 0; ni < 8; ni++) {
            int8_t sv[4];
#pragma unroll
            for (int e = 0; e < 4; e++) {
                float v = acc[mi][ni][e];
                sv[e] = (int8_t)spike_of(v);
                bool unc = (fabsf(v - 0.5f) < MARGIN) || (fabsf(v + 0.5f) < MARGIN);
                unsigned msk = __ballot_sync(0xffffffffu, unc);
                if (msk) {
                    int ldr = __ffs(msk) - 1;
                    int base = 0;
                    if (lane == ldr) base = atomicAdd(&g_nfix, __popc(msk));
                    base = __shfl_sync(0xffffffffu, base, ldr);
                    if (unc) {
                        int mg = m0 + warpM * 32 + mi * 16 + g + ((e >> 1) ? 8 : 0);
                        int og = o0 + warpN * 64 + ni * 8 + tig * 2 + (e & 1);
                        int pos = base + __popc(msk & ((1u << lane) - 1));
                        if (pos < FIXCAP) g_fix_list[pos] = mg * O3_ + og;
                    }
                }
            }
            int n1 = nb + mi * 16 + g;
            int d = ni * 8 + tig * 2;
            char2 v0, v1;
            v0.x = sv[0]; v0.y = sv[1];
            v1.x = sv[2]; v1.y = sv[3];
            *(char2*)&g_spk[tt][bh][n1][d]     = v0;
            *(char2*)&g_spk[tt][bh][n1 + 8][d] = v1;
        }
    }
}

// ---------------------------------------------------------------------------
// Kernel 5: fixup — exact fp32 warp-dots for listed uncertain elements.
// ---------------------------------------------------------------------------
__global__ void __launch_bounds__(256) fixup_kernel(const float* __restrict__ x,
                                                    const float* __restrict__ w) {
    const int lane = threadIdx.x & 31;
    const int gw = (blockIdx.x * blockDim.x + threadIdx.x) >> 5;
    const int nw = (gridDim.x * blockDim.x) >> 5;
    int nfix = g_nfix;
    if (nfix > FIXCAP) nfix = FIXCAP;

    for (int i = gw; i < nfix; i += nw) {
        int code = g_fix_list[i];
        int m = code / O3_;
        int o = code - m * O3_;
        const float4* xp = (const float4*)(x + (size_t)m * C_);
        const float4* wp = (const float4*)(w + (size_t)o * C_);
        float s = 0.0f;
#pragma unroll
        for (int c = 0; c < 6; c++) {
            float4 xv = xp[lane + c * 32];
            float4 wv = wp[lane + c * 32];
            s += xv.x * wv.x + xv.y * wv.y + xv.z * wv.z + xv.w * wv.w;
        }
#pragma unroll
        for (int off = 16; off; off >>= 1)
            s += __shfl_xor_sync(0xffffffffu, s, off);
        if (lane == 0) {
            int tt = o / 768, rem = o - tt * 768;
            g_spk[tt][(m >> 10) * H_ + (rem >> 6)][m & 1023][rem & 63] =
                (int8_t)spike_of(s);
        }
    }
}

// ---------------------------------------------------------------------------
// Kernel 6: FUSED attention, 8 warps, two 4-warp groups split 16 K-chunks.
// Dynamic smem: ssq 4KB @0, ssk[2] 4KB @4096/@8192, sd 64 x 1040B @12288.
// ---------------------------------------------------------------------------
#define ATTN_DSMEM (12288 + 64 * 1040)

__global__ void __launch_bounds__(256) attn_kernel() {
    extern __shared__ char dyn[];
    char* ssq = dyn;
    char* sd  = dyn + 12288;
    const int t = threadIdx.x;
    const int lane = t & 31, wid = t >> 5;
    const int wg = t >> 7;            // warp group 0/1
    const int tg = t & 127;           // thread-in-group
    const int wrp2 = (t >> 5) & 3;    // warp-in-group
    const int gid = lane >> 2, tig = lane & 3;
    const int bh = blockIdx.y, n0 = blockIdx.x * 64;
    const int b = bh / H_, h = bh - b * H_;

    {   // ssq: 4KB loaded by all 256 threads
        const int4* src = (const int4*)&g_spk[0][bh][n0][0];
        ((int4*)ssq)[t] = src[t];
    }
    __syncthreads();

    int afr[2][4];
#pragma unroll
    for (int ks = 0; ks < 2; ks++) {
        int r = wrp2 * 16 + gid;
        afr[ks][0] = *(const int*)(ssq + r * 64 + ks * 32 + tig * 4);
        afr[ks][1] = *(const int*)(ssq + (r + 8) * 64 + ks * 32 + tig * 4);
        afr[ks][2] = *(const int*)(ssq + r * 64 + ks * 32 + 16 + tig * 4);
        afr[ks][3] = *(const int*)(ssq + (r + 8) * 64 + ks * 32 + 16 + tig * 4);
    }

    char* ssk = dyn + 4096 + wg * 4096;
    for (int i = 0; i < 8; i++) {
        const int mc = wg * 8 + i;
        __syncthreads();
        {   // each group loads its own 4KB K tile
            const int4* src = (const int4*)&g_spk[1][bh][mc * 64][0];
            int4* dst = (int4*)ssk;
            dst[tg] = src[tg]; dst[tg + 128] = src[tg + 128];
        }
        __syncthreads();
#pragma unroll
        for (int c = 0; c < 8; c++) {
            int c0 = 0, c1 = 0, c2 = 0, c3 = 0;
#pragma unroll
            for (int ks = 0; ks < 2; ks++) {
                int b0 = *(const int*)(ssk + (c * 8 + gid) * 64 + ks * 32 + tig * 4);
                int b1 = *(const int*)(ssk + (c * 8 + gid) * 64 + ks * 32 + 16 + tig * 4);
                asm volatile(
                    "mma.sync.aligned.m16n8k32.row.col.s32.s8.s8.s32 "
                    "{%0,%1,%2,%3}, {%4,%5,%6,%7}, {%8,%9}, {%0,%1,%2,%3};"
                    : "+r"(c0), "+r"(c1), "+r"(c2), "+r"(c3)
                    : "r"(afr[ks][0]), "r"(afr[ks][1]), "r"(afr[ks][2]), "r"(afr[ks][3]),
                      "r"(b0), "r"(b1));
            }
            int row = wrp2 * 16 + gid;
            int col = mc * 64 + c * 8 + tig * 2;
            char2 lo; lo.x = (char)c0; lo.y = (char)c1;
            char2 hi; hi.x = (char)c2; hi.y = (char)c3;
            *(char2*)(sd + row * 1040 + col)       = lo;
            *(char2*)(sd + (row + 8) * 1040 + col) = hi;
        }
    }
    __syncthreads();

    // Phase 2: 8 warps x 8 rows (integer reject; exact path is rare)
    for (int r = 0; r < 8; r++) {
        const int row = wid * 8 + r;
        const char* rp = sd + row * 1040;
        int4 v0 = ((const int4*)rp)[lane];
        int4 v1 = ((const int4*)rp)[lane + 32];
        int words[8] = {v0.x, v0.y, v0.z, v0.w, v1.x, v1.y, v1.z, v1.w};

        // SIMD byte max
        int mxw = words[0];
#pragma unroll
        for (int wi = 1; wi < 8; wi++) mxw = __vmaxs4(mxw, words[wi]);
#pragma unroll
        for (int off = 16; off; off >>= 1)
            mxw = __vmaxs4(mxw, __shfl_xor_sync(0xffffffffu, mxw, off));
        int lmax = max(max((mxw << 24) >> 24, (mxw << 16) >> 24),
                       max((mxw << 8) >> 24,  mxw >> 24));

        // strong reject: count elements >= lmax - 24 (each contributes >= e^-3
        // to s). cnt >= 22 -> s >= 1 + 21*e^-3 = 2.0456 > 2 -> no spike.
        int t24 = lmax - 24;
        int tspl = (t24 & 0xff) * 0x01010101;
        int cnt = 0;
#pragma unroll
        for (int wi = 0; wi < 8; wi++)
            cnt += __popc(__vcmpges4(words[wi], tspl));
#pragma unroll
        for (int off = 16; off; off >>= 1)
            cnt += __shfl_xor_sync(0xffffffffu, cnt, off);

        int* dst = (int*)&g_s[b * N_ + n0 + row][h * D_];
        if (cnt >= 22 * 8) {    // popc counts 8 bits per passing byte
            if (lane < 16) dst[lane] = 0;
            continue;
        }

        // exact path (very rare): argmax + precise expf sum (reference math)
        float s = 0.0f;
        int larg = 0x7fffffff;
#pragma unroll
        for (int wi = 0; wi < 8; wi++) {
            int colbase = (wi < 4) ? (lane * 16 + wi * 4)
                                   : (512 + lane * 16 + (wi - 4) * 4);
#pragma unroll
            for (int j = 0; j < 4; j++) {
                int val = (words[wi] << (24 - 8 * j)) >> 24;
                s += expf(0.125f * (float)(val - lmax));
                if (val == lmax) larg = min(larg, colbase + j);
            }
        }
#pragma unroll
        for (int off = 16; off; off >>= 1) {
            s    += __shfl_xor_sync(0xffffffffu, s, off);
            larg  = min(larg, __shfl_xor_sync(0xffffffffu, larg, off));
        }
        float p = 1.0f / s;
        bool spk = (p + 0.5f) >= 1.0f;
        if (spk) {
            const int* src = (const int*)&g_spk[2][bh][larg][0];
            if (lane < 16) dst[lane] = src[lane];
            if (lane == 0) g_flag[b * N_ + n0 + row] = 1;
        } else {
            if (lane < 16) dst[lane] = 0;
        }
    }
}

// ---------------------------------------------------------------------------
// Kernel 7: output projection (fp32 exact) + final IF, zero-tile skip.
// ---------------------------------------------------------------------------
__global__ void __launch_bounds__(256) proj_kernel(const float* __restrict__ wp,
                                                   float* __restrict__ out) {
    __shared__ float As[16][64];
    __shared__ float Bs[16][64];
    __shared__ int s_any;
    const int t = threadIdx.x;
    const int tx = t & 15, ty = t >> 4;
    const int m0 = blockIdx.y * 64, o0 = blockIdx.x * 64;
    const int lr = t >> 2, lc = (t & 3) * 4;

    if (t == 0) s_any = 0;
    __syncthreads();
    if (t < 64 && g_flag[m0 + t]) s_any = 1;
    __syncthreads();
    if (!s_any) {
        float4 z = make_float4(0.f, 0.f, 0.f, 0.f);
#pragma unroll
        for (int p = 0; p < 4; p++)
            *(float4*)&out[(size_t)(m0 + lr) * 768 + o0 + (t & 3) * 4 + p * 16] = z;
        return;
    }

    float acc[4][4] = {};
    for (int k0 = 0; k0 < 768; k0 += 16) {
        int    aw = *(const int*)&g_s[m0 + lr][k0 + lc];
        float4 bv = *(const float4*)&wp[(size_t)(o0 + lr) * 768 + k0 + lc];
        __syncthreads();
        As[lc + 0][lr] = (float)((aw << 24) >> 24);
        As[lc + 1][lr] = (float)((aw << 16) >> 24);
        As[lc + 2][lr] = (float)((aw << 8)  >> 24);
        As[lc + 3][lr] = (float)( aw        >> 24);
        Bs[lc + 0][lr] = bv.x; Bs[lc + 1][lr] = bv.y;
        Bs[lc + 2][lr] = bv.z; Bs[lc + 3][lr] = bv.w;
        __syncthreads();
#pragma unroll
        for (int k = 0; k < 16; k++) {
            float4 a = *(const float4*)&As[k][ty * 4];
            float4 b = *(const float4*)&Bs[k][tx * 4];
            float ar[4] = {a.x, a.y, a.z, a.w};
            float br[4] = {b.x, b.y, b.z, b.w};
#pragma unroll
            for (int i = 0; i < 4; i++)
#pragma unroll
                for (int j = 0; j < 4; j++)
                    acc[i][j] = fmaf(ar[i], br[j], acc[i][j]);
        }
    }
#pragma unroll
    for (int i = 0; i < 4; i++) {
        int m = m0 + ty * 4 + i;
#pragma unroll
        for (int j = 0; j < 4; j++) {
            int o = o0 + tx * 4 + j;
            out[(size_t)m * 768 + o] = (float)spike_of(acc[i][j]);
        }
    }
}

// ---------------------------------------------------------------------------
extern "C" void kernel_launch(void* const* d_in, const int* in_sizes, int n_in,
                              void* d_out, int out_size) {
    const float* x      = (const float*)d_in[0];
    const float* w_qkv  = (const float*)d_in[1];
    const float* w_proj = (const float*)d_in[2];
    float* out = (float*)d_out;

    cudaFuncSetAttribute(qkv_mma_kernel,
                         cudaFuncAttributeMaxDynamicSharedMemorySize, QKV_DSMEM);
    cudaFuncSetAttribute(attn_kernel,
                         cudaFuncAttributeMaxDynamicSharedMemorySize, ATTN_DSMEM);

    convert_x_kernel<<<960, 256>>>(x);          // launch 1
    convert_w_kernel<<<480, 256>>>(w_qkv);      // launch 2
    init_kernel<<<8, 1024>>>();                 // launch 3
    qkv_mma_kernel<<<dim3(18, 64), 256, QKV_DSMEM>>>();   // launch 4 (profiled)
    fixup_kernel<<<512, 256>>>(x, w_qkv);       // launch 5
    attn_kernel<<<dim3(16, 96), 256, ATTN_DSMEM>>>();     // launch 6
    proj_kernel<<<dim3(12, 128), 256>>>(w_proj, out);     // launch 7
}

// round 10
// speedup vs baseline: 1.4419x; 1.0798x over previous
#include <cuda_runtime.h>
#include <cuda_bf16.h>
#include <cstdint>

#define B_   8
#define N_   1024
#define C_   768
#define H_   12
#define D_   64
#define BH_  96
#define M_   8192
#define O3_  2304
#define FIXCAP (1 << 21)

// Scratch (static __device__ — no allocation in kernel_launch)
__device__ __align__(16) int8_t g_spk[3][BH_][N_][D_];   // q/k/v ternary spikes
__device__ __align__(16) int8_t g_s[M_][C_];             // post-attention spikes
__device__ int    g_flag[M_];                            // per-row spike flag
__device__ int    g_nfix;                                // uncertain-element count
__device__ int    g_fix_list[FIXCAP];                    // packed m*2304+o
// x hi/lo planes in MMA A-fragment-permuted layout:
//   [m_grp 512][k_grp 48][512B tile]; tile: (g*4+tig)*16 + r*4 + b*2
__device__ __align__(16) int8_t g_xhp[512 * 48 * 512];
__device__ __align__(16) int8_t g_xlp[512 * 48 * 512];
// w_qkv hi/lo planes in MMA B-fragment-permuted layout:
//   [o_grp 288][k_grp 48][256B tile]; tile: lane*8 + breg*4 + (k&1)*2
__device__ __align__(16) int8_t g_whp[288 * 48 * 256];
__device__ __align__(16) int8_t g_wlp[288 * 48 * 256];

#define MARGIN 4e-4f

__device__ __forceinline__ int spike_of(float v) {
    float u = v + 0.5f;                        // replicate reference op order
    return (u >= 1.0f) ? 1 : ((u < 0.0f) ? -1 : 0);
}

// ---------------------------------------------------------------------------
// Kernel 1: fp32 -> bf16 hi/lo split of x, permuted to MMA A-fragment layout.
// (m,c): tile (m>>4, c>>4); lane slot = (m&7)*4 + ((c&7)>>1);
// r = ((m>>3)&1) + ((c>>3)&1)*2; byte = (c&1)*2.  (a0..a3 reg order)
// ---------------------------------------------------------------------------
__global__ void __launch_bounds__(256) convert_x_kernel(const float* __restrict__ x) {
    const int stride = gridDim.x * blockDim.x;
    const int np = M_ * C_ / 2;
    for (int j = blockIdx.x * blockDim.x + threadIdx.x; j < np; j += stride) {
        int m = (2 * j) / C_;
        int c = (2 * j) % C_;
        float2 v = *(const float2*)(x + (size_t)m * C_ + c);
        __nv_bfloat16 h0 = __float2bfloat16(v.x);
        __nv_bfloat16 l0 = __float2bfloat16(v.x - __bfloat162float(h0));
        __nv_bfloat16 h1 = __float2bfloat16(v.y);
        __nv_bfloat16 l1 = __float2bfloat16(v.y - __bfloat162float(h1));
        int kgrp = c >> 4, kin = c & 15;
        int g = m & 7, rbit = (m >> 3) & 1;
        int r = rbit + (kin >> 3) * 2;
        int tig = (kin & 7) >> 1;
        size_t dst = (size_t)(m >> 4) * 24576 + (size_t)kgrp * 512
                   + (g * 4 + tig) * 16 + r * 4;
        __nv_bfloat162 hp; hp.x = h0; hp.y = h1;
        __nv_bfloat162 lp; lp.x = l0; lp.y = l1;
        *(__nv_bfloat162*)(g_xhp + dst) = hp;
        *(__nv_bfloat162*)(g_xlp + dst) = lp;
    }
}

// ---------------------------------------------------------------------------
// Kernel 2: fp32 -> bf16 hi/lo split of w_qkv, MMA B-fragment layout.
// ---------------------------------------------------------------------------
__global__ void __launch_bounds__(256) convert_w_kernel(const float* __restrict__ w) {
    const int stride = gridDim.x * blockDim.x;
    const int np = O3_ * C_ / 2;
    for (int j = blockIdx.x * blockDim.x + threadIdx.x; j < np; j += stride) {
        int o = (2 * j) / C_;
        int c = (2 * j) % C_;
        float2 v = *(const float2*)(w + (size_t)o * C_ + c);
        __nv_bfloat16 h0 = __float2bfloat16(v.x);
        __nv_bfloat16 l0 = __float2bfloat16(v.x - __bfloat162float(h0));
        __nv_bfloat16 h1 = __float2bfloat16(v.y);
        __nv_bfloat16 l1 = __float2bfloat16(v.y - __bfloat162float(h1));
        int kgrp = c >> 4, kin = c & 15;
        int lanep = ((o & 7) << 2) | ((kin & 7) >> 1);
        int breg  = kin >> 3;
        size_t dst = (size_t)(o >> 3) * 12288 + (size_t)kgrp * 256
                   + lanep * 8 + breg * 4;
        __nv_bfloat162 hp; hp.x = h0; hp.y = h1;
        __nv_bfloat162 lp; lp.x = l0; lp.y = l1;
        *(__nv_bfloat162*)(g_whp + dst) = hp;
        *(__nv_bfloat162*)(g_wlp + dst) = lp;
    }
}

// ---------------------------------------------------------------------------
// Kernel 3: zero flags + fixup counter (deterministic across graph replays)
// ---------------------------------------------------------------------------
__global__ void init_kernel() {
    int i = blockIdx.x * blockDim.x + threadIdx.x;
    if (i < M_) g_flag[i] = 0;
    if (i == 0) g_nfix = 0;
}

// ---------------------------------------------------------------------------
// Kernel 4 (profiled slot): QKV GEMM, bf16-split mma.sync (hh+hl+lh).
// 3-stage cp.async pipeline, ONE __syncthreads per K-iteration.
// Stage: Ah 8K | Al 8K | Bh 8K | Bl 8K = 32768 B; 3 stages = 98304 B.
// A fragments: 1 LDS.128; B fragments: 1 LDS.64.
// ---------------------------------------------------------------------------
#define STG_B   32768
#define QKV_DSMEM 98304

__device__ __forceinline__ void mma_bf16(float* c, const int* a, const int* b) {
    asm volatile("mma.sync.aligned.m16n8k16.row.col.f32.bf16.bf16.f32 "
        "{%0,%1,%2,%3}, {%4,%5,%6,%7}, {%8,%9}, {%0,%1,%2,%3};"
        : "+f"(c[0]), "+f"(c[1]), "+f"(c[2]), "+f"(c[3])
        : "r"(a[0]), "r"(a[1]), "r"(a[2]), "r"(a[3]), "r"(b[0]), "r"(b[1]));
}

__global__ void __launch_bounds__(256) qkv_mma_kernel() {
    extern __shared__ char dyn[];
    uint32_t sbase;
    asm("{ .reg .u64 tmp; cvta.to.shared.u64 tmp, %1; cvt.u32.u64 %0, tmp; }"
        : "=r"(sbase) : "l"(dyn));
    const int t = threadIdx.x, lane = t & 31, wid = t >> 5;
    const int g = lane >> 2, tig = lane & 3;
    const int warpM = wid & 3, warpN = wid >> 2;
    const int o0 = blockIdx.x * 128, m0 = blockIdx.y * 128;

    float acc[2][8][4] = {};

#define PREFETCH(st, it) do {                                                  \
    int _s = (st) * STG_B;                                                     \
    _Pragma("unroll")                                                          \
    for (int _c = 0; _c < 2; _c++) {                                           \
        int ch = t + _c * 256;                                                 \
        int m_idx = ch >> 6, koff = (ch >> 5) & 1, aoff = (ch & 31) * 16;      \
        size_t ga = (size_t)((m0 >> 4) + m_idx) * 24576                        \
                  + (size_t)((it) * 2 + koff) * 512 + aoff;                    \
        uint32_t adst = (uint32_t)(m_idx * 1024 + koff * 512 + aoff);          \
        asm volatile("cp.async.cg.shared.global [%0], [%1], 16;"               \
                     :: "r"(sbase + _s + adst), "l"(g_xhp + ga));              \
        asm volatile("cp.async.cg.shared.global [%0], [%1], 16;"               \
                     :: "r"(sbase + _s + 8192 + adst), "l"(g_xlp + ga));       \
        int ogr = ch >> 5, woff = (ch & 31) * 16;                              \
        size_t gb = (size_t)((o0 >> 3) + ogr) * 12288 + (size_t)(it) * 512     \
                  + woff;                                                      \
        uint32_t bdst = (uint32_t)(ogr * 512 + woff);                          \
        asm volatile("cp.async.cg.shared.global [%0], [%1], 16;"               \
                     :: "r"(sbase + _s + 16384 + bdst), "l"(g_whp + gb));      \
        asm volatile("cp.async.cg.shared.global [%0], [%1], 16;"               \
                     :: "r"(sbase + _s + 24576 + bdst), "l"(g_wlp + gb));      \
    } } while (0)

    PREFETCH(0, 0);
    asm volatile("cp.async.commit_group;");
    PREFETCH(1, 1);
    asm volatile("cp.async.commit_group;");

    int stg_idx = 0;
    for (int it = 0; it < 24; it++) {
        if (it < 23) asm volatile("cp.async.wait_group 1;");
        else         asm volatile("cp.async.wait_group 0;");
        __syncthreads();
        if (it + 2 < 24) {
            int pst = stg_idx + 2; if (pst >= 3) pst -= 3;
            PREFETCH(pst, it + 2);
            asm volatile("cp.async.commit_group;");
        }

        const char* stg = dyn + stg_idx * STG_B;
#pragma unroll
        for (int ks = 0; ks < 2; ks++) {
            int ah[2][4], al[2][4];
#pragma unroll
            for (int mi = 0; mi < 2; mi++) {
                uint32_t aoff = (uint32_t)((warpM * 2 + mi) * 1024 + ks * 512
                                           + lane * 16);
                int4 avh = *(const int4*)(stg + aoff);
                int4 avl = *(const int4*)(stg + 8192 + aoff);
                ah[mi][0] = avh.x; ah[mi][1] = avh.y;
                ah[mi][2] = avh.z; ah[mi][3] = avh.w;
                al[mi][0] = avl.x; al[mi][1] = avl.y;
                al[mi][2] = avl.z; al[mi][3] = avl.w;
            }
#pragma unroll
            for (int ni = 0; ni < 8; ni++) {
                int boff = (warpN * 8 + ni) * 512 + ks * 256 + lane * 8;
                int2 bh2 = *(const int2*)(stg + 16384 + boff);
                int2 bl2 = *(const int2*)(stg + 24576 + boff);
                int bhf[2] = { bh2.x, bh2.y };
                int blf[2] = { bl2.x, bl2.y };
#pragma unroll
                for (int mi = 0; mi < 2; mi++) {
                    mma_bf16(acc[mi][ni], ah[mi], bhf);
                    mma_bf16(acc[mi][ni], ah[mi], blf);
                    mma_bf16(acc[mi][ni], al[mi], bhf);
                }
            }
        }
        if (++stg_idx == 3) stg_idx = 0;
    }

    // Epilogue: provisional spikes + warp-aggregated push of uncertain coords
    const int tt = o0 / 768;
    const int h0 = ((o0 % 768) >> 6) + warpN;
    const int bh = (m0 >> 10) * H_ + h0;
    const int nb = (m0 & 1023) + warpM * 32;
#pragma unroll
    for (int mi = 0; mi < 2; mi++) {
#pragma unroll
        for (int ni = 0; ni < 8; ni++) {
            int8_t sv[4];
#pragma unroll
            for (int e = 0; e < 4; e++) {
                float v = acc[mi][ni][e];
                sv[e] = (int8_t)spike_of(v);
                bool unc = (fabsf(v - 0.5f) < MARGIN) || (fabsf(v + 0.5f) < MARGIN);
                unsigned msk = __ballot_sync(0xffffffffu, unc);
                if (msk) {
                    int ldr = __ffs(msk) - 1;
                    int base = 0;
                    if (lane == ldr) base = atomicAdd(&g_nfix, __popc(msk));
                    base = __shfl_sync(0xffffffffu, base, ldr);
                    if (unc) {
                        int mg = m0 + warpM * 32 + mi * 16 + g + ((e >> 1) ? 8 : 0);
                        int og = o0 + warpN * 64 + ni * 8 + tig * 2 + (e & 1);
                        int pos = base + __popc(msk & ((1u << lane) - 1));
                        if (pos < FIXCAP) g_fix_list[pos] = mg * O3_ + og;
                    }
                }
            }
            int n1 = nb + mi * 16 + g;
            int d = ni * 8 + tig * 2;
            char2 v0, v1;
            v0.x = sv[0]; v0.y = sv[1];
            v1.x = sv[2]; v1.y = sv[3];
            *(char2*)&g_spk[tt][bh][n1][d]     = v0;
            *(char2*)&g_spk[tt][bh][n1 + 8][d] = v1;
        }
    }
}

// ---------------------------------------------------------------------------
// Kernel 5: fixup — exact fp32 warp-dots for listed uncertain elements.
// ---------------------------------------------------------------------------
__global__ void __launch_bounds__(256) fixup_kernel(const float* __restrict__ x,
                                                    const float* __restrict__ w) {
    const int lane = threadIdx.x & 31;
    const int gw = (blockIdx.x * blockDim.x + threadIdx.x) >> 5;
    const int nw = (gridDim.x * blockDim.x) >> 5;
    int nfix = g_nfix;
    if (nfix > FIXCAP) nfix = FIXCAP;

    for (int i = gw; i < nfix; i += nw) {
        int code = g_fix_list[i];
        int m = code / O3_;
        int o = code - m * O3_;
        const float4* xp = (const float4*)(x + (size_t)m * C_);
        const float4* wp = (const float4*)(w + (size_t)o * C_);
        float s = 0.0f;
#pragma unroll
        for (int c = 0; c < 6; c++) {
            float4 xv = xp[lane + c * 32];
            float4 wv = wp[lane + c * 32];
            s += xv.x * wv.x + xv.y * wv.y + xv.z * wv.z + xv.w * wv.w;
        }
#pragma unroll
        for (int off = 16; off; off >>= 1)
            s += __shfl_xor_sync(0xffffffffu, s, off);
        if (lane == 0) {
            int tt = o / 768, rem = o - tt * 768;
            g_spk[tt][(m >> 10) * H_ + (rem >> 6)][m & 1023][rem & 63] =
                (int8_t)spike_of(s);
        }
    }
}

// ---------------------------------------------------------------------------
// Kernel 6: FUSED attention, 8 warps, two 4-warp groups split 16 K-chunks.
// Dynamic smem: ssq 4KB @0, ssk[2] 4KB @4096/@8192, sd 64 x 1040B @12288.
// ---------------------------------------------------------------------------
#define ATTN_DSMEM (12288 + 64 * 1040)

__global__ void __launch_bounds__(256) attn_kernel() {
    extern __shared__ char dyn[];
    char* ssq = dyn;
    char* sd  = dyn + 12288;
    const int t = threadIdx.x;
    const int lane = t & 31, wid = t >> 5;
    const int wg = t >> 7;            // warp group 0/1
    const int tg = t & 127;           // thread-in-group
    const int wrp2 = (t >> 5) & 3;    // warp-in-group
    const int gid = lane >> 2, tig = lane & 3;
    const int bh = blockIdx.y, n0 = blockIdx.x * 64;
    const int b = bh / H_, h = bh - b * H_;

    {   // ssq: 4KB loaded by all 256 threads
        const int4* src = (const int4*)&g_spk[0][bh][n0][0];
        ((int4*)ssq)[t] = src[t];
    }
    __syncthreads();

    int afr[2][4];
#pragma unroll
    for (int ks = 0; ks < 2; ks++) {
        int r = wrp2 * 16 + gid;
        afr[ks][0] = *(const int*)(ssq + r * 64 + ks * 32 + tig * 4);
        afr[ks][1] = *(const int*)(ssq + (r + 8) * 64 + ks * 32 + tig * 4);
        afr[ks][2] = *(const int*)(ssq + r * 64 + ks * 32 + 16 + tig * 4);
        afr[ks][3] = *(const int*)(ssq + (r + 8) * 64 + ks * 32 + 16 + tig * 4);
    }

    char* ssk = dyn + 4096 + wg * 4096;
    for (int i = 0; i < 8; i++) {
        const int mc = wg * 8 + i;
        __syncthreads();
        {   // each group loads its own 4KB K tile
            const int4* src = (const int4*)&g_spk[1][bh][mc * 64][0];
            int4* dst = (int4*)ssk;
            dst[tg] = src[tg]; dst[tg + 128] = src[tg + 128];
        }
        __syncthreads();
#pragma unroll
        for (int c = 0; c < 8; c++) {
            int c0 = 0, c1 = 0, c2 = 0, c3 = 0;
#pragma unroll
            for (int ks = 0; ks < 2; ks++) {
                int b0 = *(const int*)(ssk + (c * 8 + gid) * 64 + ks * 32 + tig * 4);
                int b1 = *(const int*)(ssk + (c * 8 + gid) * 64 + ks * 32 + 16 + tig * 4);
                asm volatile(
                    "mma.sync.aligned.m16n8k32.row.col.s32.s8.s8.s32 "
                    "{%0,%1,%2,%3}, {%4,%5,%6,%7}, {%8,%9}, {%0,%1,%2,%3};"
                    : "+r"(c0), "+r"(c1), "+r"(c2), "+r"(c3)
                    : "r"(afr[ks][0]), "r"(afr[ks][1]), "r"(afr[ks][2]), "r"(afr[ks][3]),
                      "r"(b0), "r"(b1));
            }
            int row = wrp2 * 16 + gid;
            int col = mc * 64 + c * 8 + tig * 2;
            char2 lo; lo.x = (char)c0; lo.y = (char)c1;
            char2 hi; hi.x = (char)c2; hi.y = (char)c3;
            *(char2*)(sd + row * 1040 + col)       = lo;
            *(char2*)(sd + (row + 8) * 1040 + col) = hi;
        }
    }
    __syncthreads();

    // Phase 2: 8 warps x 8 rows (integer reject; exact path is rare)
    for (int r = 0; r < 8; r++) {
        const int row = wid * 8 + r;
        const char* rp = sd + row * 1040;
        int4 v0 = ((const int4*)rp)[lane];
        int4 v1 = ((const int4*)rp)[lane + 32];
        int words[8] = {v0.x, v0.y, v0.z, v0.w, v1.x, v1.y, v1.z, v1.w};

        // SIMD byte max
        int mxw = words[0];
#pragma unroll
        for (int wi = 1; wi < 8; wi++) mxw = __vmaxs4(mxw, words[wi]);
#pragma unroll
        for (int off = 16; off; off >>= 1)
            mxw = __vmaxs4(mxw, __shfl_xor_sync(0xffffffffu, mxw, off));
        int lmax = max(max((mxw << 24) >> 24, (mxw << 16) >> 24),
                       max((mxw << 8) >> 24,  mxw >> 24));

        // strong reject: count elements >= lmax - 24 (each contributes >= e^-3
        // to s). cnt >= 22 -> s >= 1 + 21*e^-3 = 2.0456 > 2 -> no spike.
        int t24 = lmax - 24;
        int tspl = (t24 & 0xff) * 0x01010101;
        int cnt = 0;
#pragma unroll
        for (int wi = 0; wi < 8; wi++)
            cnt += __popc(__vcmpges4(words[wi], tspl));
#pragma unroll
        for (int off = 16; off; off >>= 1)
            cnt += __shfl_xor_sync(0xffffffffu, cnt, off);

        int* dst = (int*)&g_s[b * N_ + n0 + row][h * D_];
        if (cnt >= 22 * 8) {    // popc counts 8 bits per passing byte
            if (lane < 16) dst[lane] = 0;
            continue;
        }

        // exact path (very rare): argmax + precise expf sum (reference math)
        float s = 0.0f;
        int larg = 0x7fffffff;
#pragma unroll
        for (int wi = 0; wi < 8; wi++) {
            int colbase = (wi < 4) ? (lane * 16 + wi * 4)
                                   : (512 + lane * 16 + (wi - 4) * 4);
#pragma unroll
            for (int j = 0; j < 4; j++) {
                int val = (words[wi] << (24 - 8 * j)) >> 24;
                s += expf(0.125f * (float)(val - lmax));
                if (val == lmax) larg = min(larg, colbase + j);
            }
        }
#pragma unroll
        for (int off = 16; off; off >>= 1) {
            s    += __shfl_xor_sync(0xffffffffu, s, off);
            larg  = min(larg, __shfl_xor_sync(0xffffffffu, larg, off));
        }
        float p = 1.0f / s;
        bool spk = (p + 0.5f) >= 1.0f;
        if (spk) {
            const int* src = (const int*)&g_spk[2][bh][larg][0];
            if (lane < 16) dst[lane] = src[lane];
            if (lane == 0) g_flag[b * N_ + n0 + row] = 1;
        } else {
            if (lane < 16) dst[lane] = 0;
        }
    }
}

// ---------------------------------------------------------------------------
// Kernel 7: output projection (fp32 exact) + final IF, zero-tile skip.
// ---------------------------------------------------------------------------
__global__ void __launch_bounds__(256) proj_kernel(const float* __restrict__ wp,
                                                   float* __restrict__ out) {
    __shared__ float As[16][64];
    __shared__ float Bs[16][64];
    __shared__ int s_any;
    const int t = threadIdx.x;
    const int tx = t & 15, ty = t >> 4;
    const int m0 = blockIdx.y * 64, o0 = blockIdx.x * 64;
    const int lr = t >> 2, lc = (t & 3) * 4;

    if (t == 0) s_any = 0;
    __syncthreads();
    if (t < 64 && g_flag[m0 + t]) s_any = 1;
    __syncthreads();
    if (!s_any) {
        float4 z = make_float4(0.f, 0.f, 0.f, 0.f);
#pragma unroll
        for (int p = 0; p < 4; p++)
            *(float4*)&out[(size_t)(m0 + lr) * 768 + o0 + (t & 3) * 4 + p * 16] = z;
        return;
    }

    float acc[4][4] = {};
    for (int k0 = 0; k0 < 768; k0 += 16) {
        int    aw = *(const int*)&g_s[m0 + lr][k0 + lc];
        float4 bv = *(const float4*)&wp[(size_t)(o0 + lr) * 768 + k0 + lc];
        __syncthreads();
        As[lc + 0][lr] = (float)((aw << 24) >> 24);
        As[lc + 1][lr] = (float)((aw << 16) >> 24);
        As[lc + 2][lr] = (float)((aw << 8)  >> 24);
        As[lc + 3][lr] = (float)( aw        >> 24);
        Bs[lc + 0][lr] = bv.x; Bs[lc + 1][lr] = bv.y;
        Bs[lc + 2][lr] = bv.z; Bs[lc + 3][lr] = bv.w;
        __syncthreads();
#pragma unroll
        for (int k = 0; k < 16; k++) {
            float4 a = *(const float4*)&As[k][ty * 4];
            float4 b = *(const float4*)&Bs[k][tx * 4];
            float ar[4] = {a.x, a.y, a.z, a.w};
            float br[4] = {b.x, b.y, b.z, b.w};
#pragma unroll
            for (int i = 0; i < 4; i++)
#pragma unroll
                for (int j = 0; j < 4; j++)
                    acc[i][j] = fmaf(ar[i], br[j], acc[i][j]);
        }
    }
#pragma unroll
    for (int i = 0; i < 4; i++) {
        int m = m0 + ty * 4 + i;
#pragma unroll
        for (int j = 0; j < 4; j++) {
            int o = o0 + tx * 4 + j;
            out[(size_t)m * 768 + o] = (float)spike_of(acc[i][j]);
        }
    }
}

// ---------------------------------------------------------------------------
extern "C" void kernel_launch(void* const* d_in, const int* in_sizes, int n_in,
                              void* d_out, int out_size) {
    const float* x      = (const float*)d_in[0];
    const float* w_qkv  = (const float*)d_in[1];
    const float* w_proj = (const float*)d_in[2];
    float* out = (float*)d_out;

    cudaFuncSetAttribute(qkv_mma_kernel,
                         cudaFuncAttributeMaxDynamicSharedMemorySize, QKV_DSMEM);
    cudaFuncSetAttribute(attn_kernel,
                         cudaFuncAttributeMaxDynamicSharedMemorySize, ATTN_DSMEM);

    convert_x_kernel<<<960, 256>>>(x);          // launch 1
    convert_w_kernel<<<480, 256>>>(w_qkv);      // launch 2
    init_kernel<<<8, 1024>>>();                 // launch 3
    qkv_mma_kernel<<<dim3(18, 64), 256, QKV_DSMEM>>>();   // launch 4 (profiled)
    fixup_kernel<<<512, 256>>>(x, w_qkv);       // launch 5
    attn_kernel<<<dim3(16, 96), 256, ATTN_DSMEM>>>();     // launch 6
    proj_kernel<<<dim3(12, 128), 256>>>(w_proj, out);     // launch 7
}

// round 11
// speedup vs baseline: 1.4893x; 1.0328x over previous
#include <cuda_runtime.h>
#include <cuda_bf16.h>
#include <cstdint>

#define B_   8
#define N_   1024
#define C_   768
#define H_   12
#define D_   64
#define BH_  96
#define M_   8192
#define O3_  2304
#define FIXCAP (1 << 21)

// Scratch (static __device__ — no allocation in kernel_launch)
__device__ __align__(16) int8_t g_spk[3][BH_][N_][D_];   // q/k/v ternary spikes
__device__ __align__(16) int8_t g_s[M_][C_];             // post-attention spikes
__device__ int    g_flag[M_];                            // per-row spike flag
__device__ int    g_nfix;                                // uncertain-element count
__device__ int    g_fix_list[FIXCAP];                    // packed m*2304+o
// x hi/lo planes in MMA A-fragment-permuted layout:
//   [m_grp 512][k_grp 48][512B tile]; slot lane*16, words r0..r3
__device__ __align__(16) int8_t g_xhp[512 * 48 * 512];
__device__ __align__(16) int8_t g_xlp[512 * 48 * 512];
// w_qkv hi/lo planes in MMA B-fragment-permuted layout:
//   [o_grp 288][k_grp 48][256B tile]; slot lane*8, words breg0/1
__device__ __align__(16) int8_t g_whp[288 * 48 * 256];
__device__ __align__(16) int8_t g_wlp[288 * 48 * 256];

#define MARGIN 4e-4f

__device__ __forceinline__ int spike_of(float v) {
    float u = v + 0.5f;                        // replicate reference op order
    return (u >= 1.0f) ? 1 : ((u < 0.0f) ? -1 : 0);
}

// ---------------------------------------------------------------------------
// Kernel 1: x -> bf16 hi/lo split, A-fragment layout, GATHER form.
// Thread = one 16B lane slot of one tile: r0:(m,c) r1:(m+8,c) r2:(m,c+8)
// r3:(m+8,c+8), each word = bf16 pair (c, c+1). Coalesced int4 stores.
// ---------------------------------------------------------------------------
__global__ void __launch_bounds__(256) convert_x_kernel(const float* __restrict__ x) {
    const int tid = blockIdx.x * 256 + threadIdx.x;   // 786432 total
    const int lane = tid & 31;
    const int tile = tid >> 5;                        // 0..24575
    const int kg = tile % 48, mg = tile / 48;
    const int g = lane >> 2, tig = lane & 3;

    uint32_t hw[4], lw[4];
#pragma unroll
    for (int r = 0; r < 4; r++) {
        int m = mg * 16 + (r & 1) * 8 + g;
        int c = kg * 16 + (r >> 1) * 8 + tig * 2;
        float2 v = *(const float2*)(x + (size_t)m * C_ + c);
        __nv_bfloat16 h0 = __float2bfloat16(v.x);
        __nv_bfloat16 l0 = __float2bfloat16(v.x - __bfloat162float(h0));
        __nv_bfloat16 h1 = __float2bfloat16(v.y);
        __nv_bfloat16 l1 = __float2bfloat16(v.y - __bfloat162float(h1));
        __nv_bfloat162 hp; hp.x = h0; hp.y = h1;
        __nv_bfloat162 lp; lp.x = l0; lp.y = l1;
        hw[r] = *(uint32_t*)&hp;
        lw[r] = *(uint32_t*)&lp;
    }
    size_t dst = (size_t)tile * 512 + lane * 16;
    int4 hv, lv;
    hv.x = hw[0]; hv.y = hw[1]; hv.z = hw[2]; hv.w = hw[3];
    lv.x = lw[0]; lv.y = lw[1]; lv.z = lw[2]; lv.w = lw[3];
    *(int4*)(g_xhp + dst) = hv;
    *(int4*)(g_xlp + dst) = lv;
}

// ---------------------------------------------------------------------------
// Kernel 2: w_qkv -> bf16 hi/lo split, B-fragment layout, GATHER form.
// Thread = one 8B lane slot (lanep == lane): breg b word = pair (c, c+1)
// with o = og*8 + (lane>>2), c = kg*16 + b*8 + (lane&3)*2.
// ---------------------------------------------------------------------------
__global__ void __launch_bounds__(256) convert_w_kernel(const float* __restrict__ w) {
    const int tid = blockIdx.x * 256 + threadIdx.x;   // 442368 total
    const int lane = tid & 31;
    const int tile = tid >> 5;                        // 0..13823
    const int kg = tile % 48, og = tile / 48;
    const int o = og * 8 + (lane >> 2);

    uint32_t hw[2], lw[2];
#pragma unroll
    for (int b = 0; b < 2; b++) {
        int c = kg * 16 + b * 8 + (lane & 3) * 2;
        float2 v = *(const float2*)(w + (size_t)o * C_ + c);
        __nv_bfloat16 h0 = __float2bfloat16(v.x);
        __nv_bfloat16 l0 = __float2bfloat16(v.x - __bfloat162float(h0));
        __nv_bfloat16 h1 = __float2bfloat16(v.y);
        __nv_bfloat16 l1 = __float2bfloat16(v.y - __bfloat162float(h1));
        __nv_bfloat162 hp; hp.x = h0; hp.y = h1;
        __nv_bfloat162 lp; lp.x = l0; lp.y = l1;
        hw[b] = *(uint32_t*)&hp;
        lw[b] = *(uint32_t*)&lp;
    }
    size_t dst = (size_t)tile * 256 + lane * 8;
    int2 hv, lv;
    hv.x = hw[0]; hv.y = hw[1];
    lv.x = lw[0]; lv.y = lw[1];
    *(int2*)(g_whp + dst) = hv;
    *(int2*)(g_wlp + dst) = lv;
}

// ---------------------------------------------------------------------------
// Kernel 3: zero flags + fixup counter (deterministic across graph replays)
// ---------------------------------------------------------------------------
__global__ void init_kernel() {
    int i = blockIdx.x * blockDim.x + threadIdx.x;
    if (i < M_) g_flag[i] = 0;
    if (i == 0) g_nfix = 0;
}

// ---------------------------------------------------------------------------
// Kernel 4 (profiled slot): QKV GEMM, bf16-split mma.sync (hh+hl+lh).
// 3-stage cp.async pipeline, ONE __syncthreads per K-iteration.
// Stage: Ah 8K | Al 8K | Bh 8K | Bl 8K = 32768 B; 3 stages = 98304 B.
// ---------------------------------------------------------------------------
#define STG_B   32768
#define QKV_DSMEM 98304

__device__ __forceinline__ void mma_bf16(float* c, const int* a, const int* b) {
    asm volatile("mma.sync.aligned.m16n8k16.row.col.f32.bf16.bf16.f32 "
        "{%0,%1,%2,%3}, {%4,%5,%6,%7}, {%8,%9}, {%0,%1,%2,%3};"
        : "+f"(c[0]), "+f"(c[1]), "+f"(c[2]), "+f"(c[3])
        : "r"(a[0]), "r"(a[1]), "r"(a[2]), "r"(a[3]), "r"(b[0]), "r"(b[1]));
}

__global__ void __launch_bounds__(256) qkv_mma_kernel() {
    extern __shared__ char dyn[];
    uint32_t sbase;
    asm("{ .reg .u64 tmp; cvta.to.shared.u64 tmp, %1; cvt.u32.u64 %0, tmp; }"
        : "=r"(sbase) : "l"(dyn));
    const int t = threadIdx.x, lane = t & 31, wid = t >> 5;
    const int g = lane >> 2, tig = lane & 3;
    const int warpM = wid & 3, warpN = wid >> 2;
    const int o0 = blockIdx.x * 128, m0 = blockIdx.y * 128;

    float acc[2][8][4] = {};

#define PREFETCH(st, it) do {                                                  \
    int _s = (st) * STG_B;                                                     \
    _Pragma("unroll")                                                          \
    for (int _c = 0; _c < 2; _c++) {                                           \
        int ch = t + _c * 256;                                                 \
        int m_idx = ch >> 6, koff = (ch >> 5) & 1, aoff = (ch & 31) * 16;      \
        size_t ga = (size_t)((m0 >> 4) + m_idx) * 24576                        \
                  + (size_t)((it) * 2 + koff) * 512 + aoff;                    \
        uint32_t adst = (uint32_t)(m_idx * 1024 + koff * 512 + aoff);          \
        asm volatile("cp.async.cg.shared.global [%0], [%1], 16;"               \
                     :: "r"(sbase + _s + adst), "l"(g_xhp + ga));              \
        asm volatile("cp.async.cg.shared.global [%0], [%1], 16;"               \
                     :: "r"(sbase + _s + 8192 + adst), "l"(g_xlp + ga));       \
        int ogr = ch >> 5, woff = (ch & 31) * 16;                              \
        size_t gb = (size_t)((o0 >> 3) + ogr) * 12288 + (size_t)(it) * 512     \
                  + woff;                                                      \
        uint32_t bdst = (uint32_t)(ogr * 512 + woff);                          \
        asm volatile("cp.async.cg.shared.global [%0], [%1], 16;"               \
                     :: "r"(sbase + _s + 16384 + bdst), "l"(g_whp + gb));      \
        asm volatile("cp.async.cg.shared.global [%0], [%1], 16;"               \
                     :: "r"(sbase + _s + 24576 + bdst), "l"(g_wlp + gb));      \
    } } while (0)

    PREFETCH(0, 0);
    asm volatile("cp.async.commit_group;");
    PREFETCH(1, 1);
    asm volatile("cp.async.commit_group;");

    int stg_idx = 0;
    for (int it = 0; it < 24; it++) {
        if (it < 23) asm volatile("cp.async.wait_group 1;");
        else         asm volatile("cp.async.wait_group 0;");
        __syncthreads();
        if (it + 2 < 24) {
            int pst = stg_idx + 2; if (pst >= 3) pst -= 3;
            PREFETCH(pst, it + 2);
            asm volatile("cp.async.commit_group;");
        }

        const char* stg = dyn + stg_idx * STG_B;
#pragma unroll
        for (int ks = 0; ks < 2; ks++) {
            int ah[2][4], al[2][4];
#pragma unroll
            for (int mi = 0; mi < 2; mi++) {
                uint32_t aoff = (uint32_t)((warpM * 2 + mi) * 1024 + ks * 512
                                           + lane * 16);
                int4 avh = *(const int4*)(stg + aoff);
                int4 avl = *(const int4*)(stg + 8192 + aoff);
                ah[mi][0] = avh.x; ah[mi][1] = avh.y;
                ah[mi][2] = avh.z; ah[mi][3] = avh.w;
                al[mi][0] = avl.x; al[mi][1] = avl.y;
                al[mi][2] = avl.z; al[mi][3] = avl.w;
            }
#pragma unroll
            for (int ni = 0; ni < 8; ni++) {
                int boff = (warpN * 8 + ni) * 512 + ks * 256 + lane * 8;
                int2 bh2 = *(const int2*)(stg + 16384 + boff);
                int2 bl2 = *(const int2*)(stg + 24576 + boff);
                int bhf[2] = { bh2.x, bh2.y };
                int blf[2] = { bl2.x, bl2.y };
#pragma unroll
                for (int mi = 0; mi < 2; mi++) {
                    mma_bf16(acc[mi][ni], ah[mi], bhf);
                    mma_bf16(acc[mi][ni], ah[mi], blf);
                    mma_bf16(acc[mi][ni], al[mi], bhf);
                }
            }
        }
        if (++stg_idx == 3) stg_idx = 0;
    }

    // Epilogue: provisional spikes; warp-aggregated push of uncertain coords.
    const int tt = o0 / 768;
    const int h0 = ((o0 % 768) >> 6) + warpN;
    const int bh = (m0 >> 10) * H_ + h0;
    const int nb = (m0 & 1023) + warpM * 32;
#pragma unroll
    for (int mi = 0; mi < 2; mi++) {
#pragma unroll
        for (int ni = 0; ni < 8; ni++) {
            int8_t sv[4];
            bool unc[4];
            bool any_unc = false;
#pragma unroll
            for (int e = 0; e < 4; e++) {
                float v = acc[mi][ni][e];
                sv[e] = (int8_t)spike_of(v);
                unc[e] = (fabsf(v - 0.5f) < MARGIN) || (fabsf(v + 0.5f) < MARGIN);
                any_unc |= unc[e];
            }
            if (__any_sync(0xffffffffu, any_unc)) {
#pragma unroll
                for (int e = 0; e < 4; e++) {
                    unsigned msk = __ballot_sync(0xffffffffu, unc[e]);
                    if (msk) {
                        int ldr = __ffs(msk) - 1;
                        int base = 0;
                        if (lane == ldr) base = atomicAdd(&g_nfix, __popc(msk));
                        base = __shfl_sync(0xffffffffu, base, ldr);
                        if (unc[e]) {
                            int mg = m0 + warpM * 32 + mi * 16 + g + ((e >> 1) ? 8 : 0);
                            int og = o0 + warpN * 64 + ni * 8 + tig * 2 + (e & 1);
                            int pos = base + __popc(msk & ((1u << lane) - 1));
                            if (pos < FIXCAP) g_fix_list[pos] = mg * O3_ + og;
                        }
                    }
                }
            }
            int n1 = nb + mi * 16 + g;
            int d = ni * 8 + tig * 2;
            char2 v0, v1;
            v0.x = sv[0]; v0.y = sv[1];
            v1.x = sv[2]; v1.y = sv[3];
            *(char2*)&g_spk[tt][bh][n1][d]     = v0;
            *(char2*)&g_spk[tt][bh][n1 + 8][d] = v1;
        }
    }
}

// ---------------------------------------------------------------------------
// Kernel 5: fixup — exact fp32 warp-dots for listed uncertain elements.
// ---------------------------------------------------------------------------
__global__ void __launch_bounds__(256) fixup_kernel(const float* __restrict__ x,
                                                    const float* __restrict__ w) {
    const int lane = threadIdx.x & 31;
    const int gw = (blockIdx.x * blockDim.x + threadIdx.x) >> 5;
    const int nw = (gridDim.x * blockDim.x) >> 5;
    int nfix = g_nfix;
    if (nfix > FIXCAP) nfix = FIXCAP;

    for (int i = gw; i < nfix; i += nw) {
        int code = g_fix_list[i];
        int m = code / O3_;
        int o = code - m * O3_;
        const float4* xp = (const float4*)(x + (size_t)m * C_);
        const float4* wp = (const float4*)(w + (size_t)o * C_);
        float s = 0.0f;
#pragma unroll
        for (int c = 0; c < 6; c++) {
            float4 xv = xp[lane + c * 32];
            float4 wv = wp[lane + c * 32];
            s += xv.x * wv.x + xv.y * wv.y + xv.z * wv.z + xv.w * wv.w;
        }
#pragma unroll
        for (int off = 16; off; off >>= 1)
            s += __shfl_xor_sync(0xffffffffu, s, off);
        if (lane == 0) {
            int tt = o / 768, rem = o - tt * 768;
            g_spk[tt][(m >> 10) * H_ + (rem >> 6)][m & 1023][rem & 63] =
                (int8_t)spike_of(s);
        }
    }
}

// ---------------------------------------------------------------------------
// Kernel 6: FUSED attention, 8 warps, two 4-warp groups split 16 K-chunks.
// Dynamic smem: ssq 4KB @0, ssk[2] 4KB @4096/@8192, sd 64 x 1040B @12288.
// ---------------------------------------------------------------------------
#define ATTN_DSMEM (12288 + 64 * 1040)

__global__ void __launch_bounds__(256) attn_kernel() {
    extern __shared__ char dyn[];
    char* ssq = dyn;
    char* sd  = dyn + 12288;
    const int t = threadIdx.x;
    const int lane = t & 31, wid = t >> 5;
    const int wg = t >> 7;            // warp group 0/1
    const int tg = t & 127;           // thread-in-group
    const int wrp2 = (t >> 5) & 3;    // warp-in-group
    const int gid = lane >> 2, tig = lane & 3;
    const int bh = blockIdx.y, n0 = blockIdx.x * 64;
    const int b = bh / H_, h = bh - b * H_;

    {   // ssq: 4KB loaded by all 256 threads
        const int4* src = (const int4*)&g_spk[0][bh][n0][0];
        ((int4*)ssq)[t] = src[t];
    }
    __syncthreads();

    int afr[2][4];
#pragma unroll
    for (int ks = 0; ks < 2; ks++) {
        int r = wrp2 * 16 + gid;
        afr[ks][0] = *(const int*)(ssq + r * 64 + ks * 32 + tig * 4);
        afr[ks][1] = *(const int*)(ssq + (r + 8) * 64 + ks * 32 + tig * 4);
        afr[ks][2] = *(const int*)(ssq + r * 64 + ks * 32 + 16 + tig * 4);
        afr[ks][3] = *(const int*)(ssq + (r + 8) * 64 + ks * 32 + 16 + tig * 4);
    }

    char* ssk = dyn + 4096 + wg * 4096;
    for (int i = 0; i < 8; i++) {
        const int mc = wg * 8 + i;
        __syncthreads();
        {   // each group loads its own 4KB K tile
            const int4* src = (const int4*)&g_spk[1][bh][mc * 64][0];
            int4* dst = (int4*)ssk;
            dst[tg] = src[tg]; dst[tg + 128] = src[tg + 128];
        }
        __syncthreads();
#pragma unroll
        for (int c = 0; c < 8; c++) {
            int c0 = 0, c1 = 0, c2 = 0, c3 = 0;
#pragma unroll
            for (int ks = 0; ks < 2; ks++) {
                int b0 = *(const int*)(ssk + (c * 8 + gid) * 64 + ks * 32 + tig * 4);
                int b1 = *(const int*)(ssk + (c * 8 + gid) * 64 + ks * 32 + 16 + tig * 4);
                asm volatile(
                    "mma.sync.aligned.m16n8k32.row.col.s32.s8.s8.s32 "
                    "{%0,%1,%2,%3}, {%4,%5,%6,%7}, {%8,%9}, {%0,%1,%2,%3};"
                    : "+r"(c0), "+r"(c1), "+r"(c2), "+r"(c3)
                    : "r"(afr[ks][0]), "r"(afr[ks][1]), "r"(afr[ks][2]), "r"(afr[ks][3]),
                      "r"(b0), "r"(b1));
            }
            int row = wrp2 * 16 + gid;
            int col = mc * 64 + c * 8 + tig * 2;
            char2 lo; lo.x = (char)c0; lo.y = (char)c1;
            char2 hi; hi.x = (char)c2; hi.y = (char)c3;
            *(char2*)(sd + row * 1040 + col)       = lo;
            *(char2*)(sd + (row + 8) * 1040 + col) = hi;
        }
    }
    __syncthreads();

    // Phase 2: 8 warps x 8 rows (integer reject; exact path is rare)
    for (int r = 0; r < 8; r++) {
        const int row = wid * 8 + r;
        const char* rp = sd + row * 1040;
        int4 v0 = ((const int4*)rp)[lane];
        int4 v1 = ((const int4*)rp)[lane + 32];
        int words[8] = {v0.x, v0.y, v0.z, v0.w, v1.x, v1.y, v1.z, v1.w};

        // SIMD byte max
        int mxw = words[0];
#pragma unroll
        for (int wi = 1; wi < 8; wi++) mxw = __vmaxs4(mxw, words[wi]);
#pragma unroll
        for (int off = 16; off; off >>= 1)
            mxw = __vmaxs4(mxw, __shfl_xor_sync(0xffffffffu, mxw, off));
        int lmax = max(max((mxw << 24) >> 24, (mxw << 16) >> 24),
                       max((mxw << 8) >> 24,  mxw >> 24));

        // strong reject: count elements >= lmax - 24 (each contributes >= e^-3
        // to s). cnt >= 22 -> s >= 1 + 21*e^-3 = 2.0456 > 2 -> no spike.
        int t24 = lmax - 24;
        int tspl = (t24 & 0xff) * 0x01010101;
        int cnt = 0;
#pragma unroll
        for (int wi = 0; wi < 8; wi++)
            cnt += __popc(__vcmpges4(words[wi], tspl));
#pragma unroll
        for (int off = 16; off; off >>= 1)
            cnt += __shfl_xor_sync(0xffffffffu, cnt, off);

        int* dst = (int*)&g_s[b * N_ + n0 + row][h * D_];
        if (cnt >= 22 * 8) {    // popc counts 8 bits per passing byte
            if (lane < 16) dst[lane] = 0;
            continue;
        }

        // exact path (very rare): argmax + precise expf sum (reference math)
        float s = 0.0f;
        int larg = 0x7fffffff;
#pragma unroll
        for (int wi = 0; wi < 8; wi++) {
            int colbase = (wi < 4) ? (lane * 16 + wi * 4)
                                   : (512 + lane * 16 + (wi - 4) * 4);
#pragma unroll
            for (int j = 0; j < 4; j++) {
                int val = (words[wi] << (24 - 8 * j)) >> 24;
                s += expf(0.125f * (float)(val - lmax));
                if (val == lmax) larg = min(larg, colbase + j);
            }
        }
#pragma unroll
        for (int off = 16; off; off >>= 1) {
            s    += __shfl_xor_sync(0xffffffffu, s, off);
            larg  = min(larg, __shfl_xor_sync(0xffffffffu, larg, off));
        }
        float p = 1.0f / s;
        bool spk = (p + 0.5f) >= 1.0f;
        if (spk) {
            const int* src = (const int*)&g_spk[2][bh][larg][0];
            if (lane < 16) dst[lane] = src[lane];
            if (lane == 0) g_flag[b * N_ + n0 + row] = 1;
        } else {
            if (lane < 16) dst[lane] = 0;
        }
    }
}

// ---------------------------------------------------------------------------
// Kernel 7: output projection (fp32 exact) + final IF, zero-tile skip.
// ---------------------------------------------------------------------------
__global__ void __launch_bounds__(256) proj_kernel(const float* __restrict__ wp,
                                                   float* __restrict__ out) {
    __shared__ float As[16][64];
    __shared__ float Bs[16][64];
    __shared__ int s_any;
    const int t = threadIdx.x;
    const int tx = t & 15, ty = t >> 4;
    const int m0 = blockIdx.y * 64, o0 = blockIdx.x * 64;
    const int lr = t >> 2, lc = (t & 3) * 4;

    if (t == 0) s_any = 0;
    __syncthreads();
    if (t < 64 && g_flag[m0 + t]) s_any = 1;
    __syncthreads();
    if (!s_any) {
        float4 z = make_float4(0.f, 0.f, 0.f, 0.f);
#pragma unroll
        for (int p = 0; p < 4; p++)
            *(float4*)&out[(size_t)(m0 + lr) * 768 + o0 + (t & 3) * 4 + p * 16] = z;
        return;
    }

    float acc[4][4] = {};
    for (int k0 = 0; k0 < 768; k0 += 16) {
        int    aw = *(const int*)&g_s[m0 + lr][k0 + lc];
        float4 bv = *(const float4*)&wp[(size_t)(o0 + lr) * 768 + k0 + lc];
        __syncthreads();
        As[lc + 0][lr] = (float)((aw << 24) >> 24);
        As[lc + 1][lr] = (float)((aw << 16) >> 24);
        As[lc + 2][lr] = (float)((aw << 8)  >> 24);
        As[lc + 3][lr] = (float)( aw        >> 24);
        Bs[lc + 0][lr] = bv.x; Bs[lc + 1][lr] = bv.y;
        Bs[lc + 2][lr] = bv.z; Bs[lc + 3][lr] = bv.w;
        __syncthreads();
#pragma unroll
        for (int k = 0; k < 16; k++) {
            float4 a = *(const float4*)&As[k][ty * 4];
            float4 b = *(const float4*)&Bs[k][tx * 4];
            float ar[4] = {a.x, a.y, a.z, a.w};
            float br[4] = {b.x, b.y, b.z, b.w};
#pragma unroll
            for (int i = 0; i < 4; i++)
#pragma unroll
                for (int j = 0; j < 4; j++)
                    acc[i][j] = fmaf(ar[i], br[j], acc[i][j]);
        }
    }
#pragma unroll
    for (int i = 0; i < 4; i++) {
        int m = m0 + ty * 4 + i;
#pragma unroll
        for (int j = 0; j < 4; j++) {
            int o = o0 + tx * 4 + j;
            out[(size_t)m * 768 + o] = (float)spike_of(acc[i][j]);
        }
    }
}

// ---------------------------------------------------------------------------
extern "C" void kernel_launch(void* const* d_in, const int* in_sizes, int n_in,
                              void* d_out, int out_size) {
    const float* x      = (const float*)d_in[0];
    const float* w_qkv  = (const float*)d_in[1];
    const float* w_proj = (const float*)d_in[2];
    float* out = (float*)d_out;

    cudaFuncSetAttribute(qkv_mma_kernel,
                         cudaFuncAttributeMaxDynamicSharedMemorySize, QKV_DSMEM);
    cudaFuncSetAttribute(attn_kernel,
                         cudaFuncAttributeMaxDynamicSharedMemorySize, ATTN_DSMEM);

    convert_x_kernel<<<3072, 256>>>(x);         // launch 1
    convert_w_kernel<<<1728, 256>>>(w_qkv);     // launch 2
    init_kernel<<<8, 1024>>>();                 // launch 3
    qkv_mma_kernel<<<dim3(18, 64), 256, QKV_DSMEM>>>();   // launch 4 (profiled)
    fixup_kernel<<<512, 256>>>(x, w_qkv);       // launch 5
    attn_kernel<<<dim3(16, 96), 256, ATTN_DSMEM>>>();     // launch 6
    proj_kernel<<<dim3(12, 128), 256>>>(w_proj, out);     // launch 7
}

// round 12
// speedup vs baseline: 1.4987x; 1.0063x over previous
#include <cuda_runtime.h>
#include <cuda_bf16.h>
#include <cstdint>

#define B_   8
#define N_   1024
#define C_   768
#define H_   12
#define D_   64
#define BH_  96
#define M_   8192
#define O3_  2304
#define FIXCAP (1 << 21)

// Scratch (static __device__ — no allocation in kernel_launch)
__device__ __align__(16) int8_t g_spk[3][BH_][N_][D_];   // q/k/v ternary spikes
__device__ __align__(16) int8_t g_s[M_][C_];             // post-attention spikes
__device__ int    g_flag[M_];                            // per-row spike flag
__device__ int    g_nfix;                                // uncertain-element count
__device__ int    g_fix_list[FIXCAP];                    // packed m*2304+o
// x hi/lo planes, A-fragment layout: [m_grp 512][k_grp 48][512B tile]
__device__ __align__(16) int8_t g_xhp[512 * 48 * 512];
__device__ __align__(16) int8_t g_xlp[512 * 48 * 512];
// w_qkv hi/lo planes, PAIRED B-fragment layout:
//   [og2 144][k_grp 48][512B tile]; lane slot 16B = frag(o half0) | frag(half1)
__device__ __align__(16) int8_t g_whp[144 * 48 * 512];
__device__ __align__(16) int8_t g_wlp[144 * 48 * 512];

#define MARGIN 4e-4f

__device__ __forceinline__ int spike_of(float v) {
    float u = v + 0.5f;                        // replicate reference op order
    return (u >= 1.0f) ? 1 : ((u < 0.0f) ? -1 : 0);
}

// ---------------------------------------------------------------------------
// Kernel 1: x -> bf16 hi/lo split, A-fragment layout, gather form.
// ---------------------------------------------------------------------------
__global__ void __launch_bounds__(256) convert_x_kernel(const float* __restrict__ x) {
    const int tid = blockIdx.x * 256 + threadIdx.x;   // 786432 total
    const int lane = tid & 31;
    const int tile = tid >> 5;                        // 0..24575
    const int kg = tile % 48, mg = tile / 48;
    const int g = lane >> 2, tig = lane & 3;

    uint32_t hw[4], lw[4];
#pragma unroll
    for (int r = 0; r < 4; r++) {
        int m = mg * 16 + (r & 1) * 8 + g;
        int c = kg * 16 + (r >> 1) * 8 + tig * 2;
        float2 v = *(const float2*)(x + (size_t)m * C_ + c);
        __nv_bfloat16 h0 = __float2bfloat16(v.x);
        __nv_bfloat16 l0 = __float2bfloat16(v.x - __bfloat162float(h0));
        __nv_bfloat16 h1 = __float2bfloat16(v.y);
        __nv_bfloat16 l1 = __float2bfloat16(v.y - __bfloat162float(h1));
        __nv_bfloat162 hp; hp.x = h0; hp.y = h1;
        __nv_bfloat162 lp; lp.x = l0; lp.y = l1;
        hw[r] = *(uint32_t*)&hp;
        lw[r] = *(uint32_t*)&lp;
    }
    size_t dst = (size_t)tile * 512 + lane * 16;
    int4 hv, lv;
    hv.x = hw[0]; hv.y = hw[1]; hv.z = hw[2]; hv.w = hw[3];
    lv.x = lw[0]; lv.y = lw[1]; lv.z = lw[2]; lv.w = lw[3];
    *(int4*)(g_xhp + dst) = hv;
    *(int4*)(g_xlp + dst) = lv;
}

// ---------------------------------------------------------------------------
// Kernel 2: w_qkv -> bf16 hi/lo split, PAIRED B-fragment layout, gather form.
// ---------------------------------------------------------------------------
__global__ void __launch_bounds__(256) convert_w_kernel(const float* __restrict__ w) {
    const int tid = blockIdx.x * 256 + threadIdx.x;   // 221184 total
    const int lane = tid & 31;
    const int tile = tid >> 5;                        // 0..6911
    const int kg = tile % 48, og2 = tile / 48;
    const int oq = lane >> 2, cq = (lane & 3) * 2;

    uint32_t hw[4], lw[4];
#pragma unroll
    for (int half = 0; half < 2; half++) {
        int o = og2 * 16 + half * 8 + oq;
#pragma unroll
        for (int b = 0; b < 2; b++) {
            int c = kg * 16 + b * 8 + cq;
            float2 v = *(const float2*)(w + (size_t)o * C_ + c);
            __nv_bfloat16 h0 = __float2bfloat16(v.x);
            __nv_bfloat16 l0 = __float2bfloat16(v.x - __bfloat162float(h0));
            __nv_bfloat16 h1 = __float2bfloat16(v.y);
            __nv_bfloat16 l1 = __float2bfloat16(v.y - __bfloat162float(h1));
            __nv_bfloat162 hp; hp.x = h0; hp.y = h1;
            __nv_bfloat162 lp; lp.x = l0; lp.y = l1;
            hw[half * 2 + b] = *(uint32_t*)&hp;
            lw[half * 2 + b] = *(uint32_t*)&lp;
        }
    }
    size_t dst = (size_t)tile * 512 + lane * 16;
    int4 hv, lv;
    hv.x = hw[0]; hv.y = hw[1]; hv.z = hw[2]; hv.w = hw[3];
    lv.x = lw[0]; lv.y = lw[1]; lv.z = lw[2]; lv.w = lw[3];
    *(int4*)(g_whp + dst) = hv;
    *(int4*)(g_wlp + dst) = lv;
}

// ---------------------------------------------------------------------------
// Kernel 3: zero flags + fixup counter (deterministic across graph replays)
// ---------------------------------------------------------------------------
__global__ void init_kernel() {
    int i = blockIdx.x * blockDim.x + threadIdx.x;
    if (i < M_) g_flag[i] = 0;
    if (i == 0) g_nfix = 0;
}

// ---------------------------------------------------------------------------
// Kernel 4 (profiled): QKV GEMM, bf16-split mma.sync, 512 thr / 16 thin warps
// (8 warpM x 2 warpN, warp tile 16x64). 3-stage cp.async, 1 sync per iter.
// ---------------------------------------------------------------------------
#define STG_B   32768
#define QKV_DSMEM 98304

__device__ __forceinline__ void mma_bf16(float* c, const int* a, const int* b) {
    asm volatile("mma.sync.aligned.m16n8k16.row.col.f32.bf16.bf16.f32 "
        "{%0,%1,%2,%3}, {%4,%5,%6,%7}, {%8,%9}, {%0,%1,%2,%3};"
        : "+f"(c[0]), "+f"(c[1]), "+f"(c[2]), "+f"(c[3])
        : "r"(a[0]), "r"(a[1]), "r"(a[2]), "r"(a[3]), "r"(b[0]), "r"(b[1]));
}

__global__ void __launch_bounds__(512, 2) qkv_mma_kernel() {
    extern __shared__ char dyn[];
    uint32_t sbase;
    asm("{ .reg .u64 tmp; cvta.to.shared.u64 tmp, %1; cvt.u32.u64 %0, tmp; }"
        : "=r"(sbase) : "l"(dyn));
    const int t = threadIdx.x, lane = t & 31, wid = t >> 5;
    const int g = lane >> 2, tig = lane & 3;
    const int warpM = wid & 7, warpN = wid >> 3;
    const int o0 = blockIdx.x * 128, m0 = blockIdx.y * 128;

    float acc[8][4] = {};

#define PREFETCH(st, it) do {                                                  \
    int _s = (st) * STG_B;                                                     \
    int mgl = t >> 6, koff = (t >> 5) & 1;                                     \
    uint32_t slot = (uint32_t)((t & 31) * 16);                                 \
    uint32_t doff = (uint32_t)(mgl * 1024 + koff * 512) + slot;                \
    size_t ga = (size_t)((m0 >> 4) + mgl) * 24576                              \
              + (size_t)((it) * 2 + koff) * 512 + slot;                        \
    size_t gb = (size_t)((o0 >> 4) + mgl) * 24576                              \
              + (size_t)((it) * 2 + koff) * 512 + slot;                        \
    asm volatile("cp.async.cg.shared.global [%0], [%1], 16;"                   \
                 :: "r"(sbase + _s + doff), "l"(g_xhp + ga));                  \
    asm volatile("cp.async.cg.shared.global [%0], [%1], 16;"                   \
                 :: "r"(sbase + _s + 8192 + doff), "l"(g_xlp + ga));           \
    asm volatile("cp.async.cg.shared.global [%0], [%1], 16;"                   \
                 :: "r"(sbase + _s + 16384 + doff), "l"(g_whp + gb));          \
    asm volatile("cp.async.cg.shared.global [%0], [%1], 16;"                   \
                 :: "r"(sbase + _s + 24576 + doff), "l"(g_wlp + gb));          \
    } while (0)

    PREFETCH(0, 0);
    asm volatile("cp.async.commit_group;");
    PREFETCH(1, 1);
    asm volatile("cp.async.commit_group;");

    int stg_idx = 0;
    for (int it = 0; it < 24; it++) {
        if (it < 23) asm volatile("cp.async.wait_group 1;");
        else         asm volatile("cp.async.wait_group 0;");
        __syncthreads();
        if (it + 2 < 24) {
            int pst = stg_idx + 2; if (pst >= 3) pst -= 3;
            PREFETCH(pst, it + 2);
            asm volatile("cp.async.commit_group;");
        }

        const char* stg = dyn + stg_idx * STG_B;
#pragma unroll
        for (int ks = 0; ks < 2; ks++) {
            int ah[4], al[4];
            {
                uint32_t aoff = (uint32_t)(warpM * 1024 + ks * 512 + lane * 16);
                int4 avh = *(const int4*)(stg + aoff);
                int4 avl = *(const int4*)(stg + 8192 + aoff);
                ah[0] = avh.x; ah[1] = avh.y; ah[2] = avh.z; ah[3] = avh.w;
                al[0] = avl.x; al[1] = avl.y; al[2] = avl.z; al[3] = avl.w;
            }
#pragma unroll
            for (int nip = 0; nip < 4; nip++) {
                uint32_t boff = (uint32_t)((warpN * 4 + nip) * 1024 + ks * 512
                                           + lane * 16);
                int4 bvh = *(const int4*)(stg + 16384 + boff);
                int4 bvl = *(const int4*)(stg + 24576 + boff);
                int bh0[2] = { bvh.x, bvh.y };
                int bh1[2] = { bvh.z, bvh.w };
                int bl0[2] = { bvl.x, bvl.y };
                int bl1[2] = { bvl.z, bvl.w };
                mma_bf16(acc[nip * 2],     ah, bh0);
                mma_bf16(acc[nip * 2],     ah, bl0);
                mma_bf16(acc[nip * 2],     al, bh0);
                mma_bf16(acc[nip * 2 + 1], ah, bh1);
                mma_bf16(acc[nip * 2 + 1], ah, bl1);
                mma_bf16(acc[nip * 2 + 1], al, bh1);
            }
        }
        if (++stg_idx == 3) stg_idx = 0;
    }

    // Epilogue: provisional spikes; warp-aggregated push of uncertain coords.
    const int tt = o0 / 768;
    const int h0 = ((o0 % 768) >> 6) + warpN;
    const int bh = (m0 >> 10) * H_ + h0;
    const int nb = (m0 & 1023) + warpM * 16;
#pragma unroll
    for (int ni = 0; ni < 8; ni++) {
        const int d = (ni >> 1) * 16 + (ni & 1) * 8 + tig * 2;
        int8_t sv[4];
        bool unc[4];
        bool any_unc = false;
#pragma unroll
        for (int e = 0; e < 4; e++) {
            float v = acc[ni][e];
            sv[e] = (int8_t)spike_of(v);
            unc[e] = (fabsf(v - 0.5f) < MARGIN) || (fabsf(v + 0.5f) < MARGIN);
            any_unc |= unc[e];
        }
        if (__any_sync(0xffffffffu, any_unc)) {
#pragma unroll
            for (int e = 0; e < 4; e++) {
                unsigned msk = __ballot_sync(0xffffffffu, unc[e]);
                if (msk) {
                    int ldr = __ffs(msk) - 1;
                    int base = 0;
                    if (lane == ldr) base = atomicAdd(&g_nfix, __popc(msk));
                    base = __shfl_sync(0xffffffffu, base, ldr);
                    if (unc[e]) {
                        int mg = m0 + warpM * 16 + g + ((e >> 1) ? 8 : 0);
                        int og = o0 + warpN * 64 + d + (e & 1);
                        int pos = base + __popc(msk & ((1u << lane) - 1));
                        if (pos < FIXCAP) g_fix_list[pos] = mg * O3_ + og;
                    }
                }
            }
        }
        int n1 = nb + g;
        char2 v0, v1;
        v0.x = sv[0]; v0.y = sv[1];
        v1.x = sv[2]; v1.y = sv[3];
        *(char2*)&g_spk[tt][bh][n1][d]     = v0;
        *(char2*)&g_spk[tt][bh][n1 + 8][d] = v1;
    }
}

// ---------------------------------------------------------------------------
// Kernel 5: fixup — exact fp32 warp-dots for listed uncertain elements.
// ---------------------------------------------------------------------------
__global__ void __launch_bounds__(256) fixup_kernel(const float* __restrict__ x,
                                                    const float* __restrict__ w) {
    const int lane = threadIdx.x & 31;
    const int gw = (blockIdx.x * blockDim.x + threadIdx.x) >> 5;
    const int nw = (gridDim.x * blockDim.x) >> 5;
    int nfix = g_nfix;
    if (nfix > FIXCAP) nfix = FIXCAP;

    for (int i = gw; i < nfix; i += nw) {
        int code = g_fix_list[i];
        int m = code / O3_;
        int o = code - m * O3_;
        const float4* xp = (const float4*)(x + (size_t)m * C_);
        const float4* wp = (const float4*)(w + (size_t)o * C_);
        float s = 0.0f;
#pragma unroll
        for (int c = 0; c < 6; c++) {
            float4 xv = xp[lane + c * 32];
            float4 wv = wp[lane + c * 32];
            s += xv.x * wv.x + xv.y * wv.y + xv.z * wv.z + xv.w * wv.w;
        }
#pragma unroll
        for (int off = 16; off; off >>= 1)
            s += __shfl_xor_sync(0xffffffffu, s, off);
        if (lane == 0) {
            int tt = o / 768, rem = o - tt * 768;
            g_spk[tt][(m >> 10) * H_ + (rem >> 6)][m & 1023][rem & 63] =
                (int8_t)spike_of(s);
        }
    }
}

// ---------------------------------------------------------------------------
// Kernel 6: FUSED attention, 8 warps, two 4-warp groups split 16 K-chunks.
// ---------------------------------------------------------------------------
#define ATTN_DSMEM (12288 + 64 * 1040)

__global__ void __launch_bounds__(256) attn_kernel() {
    extern __shared__ char dyn[];
    char* ssq = dyn;
    char* sd  = dyn + 12288;
    const int t = threadIdx.x;
    const int lane = t & 31, wid = t >> 5;
    const int wg = t >> 7;
    const int tg = t & 127;
    const int wrp2 = (t >> 5) & 3;
    const int gid = lane >> 2, tig = lane & 3;
    const int bh = blockIdx.y, n0 = blockIdx.x * 64;
    const int b = bh / H_, h = bh - b * H_;

    {
        const int4* src = (const int4*)&g_spk[0][bh][n0][0];
        ((int4*)ssq)[t] = src[t];
    }
    __syncthreads();

    int afr[2][4];
#pragma unroll
    for (int ks = 0; ks < 2; ks++) {
        int r = wrp2 * 16 + gid;
        afr[ks][0] = *(const int*)(ssq + r * 64 + ks * 32 + tig * 4);
        afr[ks][1] = *(const int*)(ssq + (r + 8) * 64 + ks * 32 + tig * 4);
        afr[ks][2] = *(const int*)(ssq + r * 64 + ks * 32 + 16 + tig * 4);
        afr[ks][3] = *(const int*)(ssq + (r + 8) * 64 + ks * 32 + 16 + tig * 4);
    }

    char* ssk = dyn + 4096 + wg * 4096;
    for (int i = 0; i < 8; i++) {
        const int mc = wg * 8 + i;
        __syncthreads();
        {
            const int4* src = (const int4*)&g_spk[1][bh][mc * 64][0];
            int4* dst = (int4*)ssk;
            dst[tg] = src[tg]; dst[tg + 128] = src[tg + 128];
        }
        __syncthreads();
#pragma unroll
        for (int c = 0; c < 8; c++) {
            int c0 = 0, c1 = 0, c2 = 0, c3 = 0;
#pragma unroll
            for (int ks = 0; ks < 2; ks++) {
                int b0 = *(const int*)(ssk + (c * 8 + gid) * 64 + ks * 32 + tig * 4);
                int b1 = *(const int*)(ssk + (c * 8 + gid) * 64 + ks * 32 + 16 + tig * 4);
                asm volatile(
                    "mma.sync.aligned.m16n8k32.row.col.s32.s8.s8.s32 "
                    "{%0,%1,%2,%3}, {%4,%5,%6,%7}, {%8,%9}, {%0,%1,%2,%3};"
                    : "+r"(c0), "+r"(c1), "+r"(c2), "+r"(c3)
                    : "r"(afr[ks][0]), "r"(afr[ks][1]), "r"(afr[ks][2]), "r"(afr[ks][3]),
                      "r"(b0), "r"(b1));
            }
            int row = wrp2 * 16 + gid;
            int col = mc * 64 + c * 8 + tig * 2;
            char2 lo; lo.x = (char)c0; lo.y = (char)c1;
            char2 hi; hi.x = (char)c2; hi.y = (char)c3;
            *(char2*)(sd + row * 1040 + col)       = lo;
            *(char2*)(sd + (row + 8) * 1040 + col) = hi;
        }
    }
    __syncthreads();

    for (int r = 0; r < 8; r++) {
        const int row = wid * 8 + r;
        const char* rp = sd + row * 1040;
        int4 v0 = ((const int4*)rp)[lane];
        int4 v1 = ((const int4*)rp)[lane + 32];
        int words[8] = {v0.x, v0.y, v0.z, v0.w, v1.x, v1.y, v1.z, v1.w};

        int mxw = words[0];
#pragma unroll
        for (int wi = 1; wi < 8; wi++) mxw = __vmaxs4(mxw, words[wi]);
#pragma unroll
        for (int off = 16; off; off >>= 1)
            mxw = __vmaxs4(mxw, __shfl_xor_sync(0xffffffffu, mxw, off));
        int lmax = max(max((mxw << 24) >> 24, (mxw << 16) >> 24),
                       max((mxw << 8) >> 24,  mxw >> 24));

        int t24 = lmax - 24;
        int tspl = (t24 & 0xff) * 0x01010101;
        int cnt = 0;
#pragma unroll
        for (int wi = 0; wi < 8; wi++)
            cnt += __popc(__vcmpges4(words[wi], tspl));
#pragma unroll
        for (int off = 16; off; off >>= 1)
            cnt += __shfl_xor_sync(0xffffffffu, cnt, off);

        int* dst = (int*)&g_s[b * N_ + n0 + row][h * D_];
        if (cnt >= 22 * 8) {
            if (lane < 16) dst[lane] = 0;
            continue;
        }

        float s = 0.0f;
        int larg = 0x7fffffff;
#pragma unroll
        for (int wi = 0; wi < 8; wi++) {
            int colbase = (wi < 4) ? (lane * 16 + wi * 4)
                                   : (512 + lane * 16 + (wi - 4) * 4);
#pragma unroll
            for (int j = 0; j < 4; j++) {
                int val = (words[wi] << (24 - 8 * j)) >> 24;
                s += expf(0.125f * (float)(val - lmax));
                if (val == lmax) larg = min(larg, colbase + j);
            }
        }
#pragma unroll
        for (int off = 16; off; off >>= 1) {
            s    += __shfl_xor_sync(0xffffffffu, s, off);
            larg  = min(larg, __shfl_xor_sync(0xffffffffu, larg, off));
        }
        float p = 1.0f / s;
        bool spk = (p + 0.5f) >= 1.0f;
        if (spk) {
            const int* src = (const int*)&g_spk[2][bh][larg][0];
            if (lane < 16) dst[lane] = src[lane];
            if (lane == 0) g_flag[b * N_ + n0 + row] = 1;
        } else {
            if (lane < 16) dst[lane] = 0;
        }
    }
}

// ---------------------------------------------------------------------------
// Kernel 7: output projection (fp32 exact) + final IF, zero-tile skip.
// ---------------------------------------------------------------------------
__global__ void __launch_bounds__(256) proj_kernel(const float* __restrict__ wp,
                                                   float* __restrict__ out) {
    __shared__ float As[16][64];
    __shared__ float Bs[16][64];
    __shared__ int s_any;
    const int t = threadIdx.x;
    const int tx = t & 15, ty = t >> 4;
    const int m0 = blockIdx.y * 64, o0 = blockIdx.x * 64;
    const int lr = t >> 2, lc = (t & 3) * 4;

    if (t == 0) s_any = 0;
    __syncthreads();
    if (t < 64 && g_flag[m0 + t]) s_any = 1;
    __syncthreads();
    if (!s_any) {
        float4 z = make_float4(0.f, 0.f, 0.f, 0.f);
#pragma unroll
        for (int p = 0; p < 4; p++)
            *(float4*)&out[(size_t)(m0 + lr) * 768 + o0 + (t & 3) * 4 + p * 16] = z;
        return;
    }

    float acc[4][4] = {};
    for (int k0 = 0; k0 < 768; k0 += 16) {
        int    aw = *(const int*)&g_s[m0 + lr][k0 + lc];
        float4 bv = *(const float4*)&wp[(size_t)(o0 + lr) * 768 + k0 + lc];
        __syncthreads();
        As[lc + 0][lr] = (float)((aw << 24) >> 24);
        As[lc + 1][lr] = (float)((aw << 16) >> 24);
        As[lc + 2][lr] = (float)((aw << 8)  >> 24);
        As[lc + 3][lr] = (float)( aw        >> 24);
        Bs[lc + 0][lr] = bv.x; Bs[lc + 1][lr] = bv.y;
        Bs[lc + 2][lr] = bv.z; Bs[lc + 3][lr] = bv.w;
        __syncthreads();
#pragma unroll
        for (int k = 0; k < 16; k++) {
            float4 a = *(const float4*)&As[k][ty * 4];
            float4 b = *(const float4*)&Bs[k][tx * 4];
            float ar[4] = {a.x, a.y, a.z, a.w};
            float br[4] = {b.x, b.y, b.z, b.w};
#pragma unroll
            for (int i = 0; i < 4; i++)
#pragma unroll
                for (int j = 0; j < 4; j++)
                    acc[i][j] = fmaf(ar[i], br[j], acc[i][j]);
        }
    }
#pragma unroll
    for (int i = 0; i < 4; i++) {
        int m = m0 + ty * 4 + i;
#pragma unroll
        for (int j = 0; j < 4; j++) {
            int o = o0 + tx * 4 + j;
            out[(size_t)m * 768 + o] = (float)spike_of(acc[i][j]);
        }
    }
}

// ---------------------------------------------------------------------------
extern "C" void kernel_launch(void* const* d_in, const int* in_sizes, int n_in,
                              void* d_out, int out_size) {
    const float* x      = (const float*)d_in[0];
    const float* w_qkv  = (const float*)d_in[1];
    const float* w_proj = (const float*)d_in[2];
    float* out = (float*)d_out;

    cudaFuncSetAttribute(qkv_mma_kernel,
                         cudaFuncAttributeMaxDynamicSharedMemorySize, QKV_DSMEM);
    cudaFuncSetAttribute(attn_kernel,
                         cudaFuncAttributeMaxDynamicSharedMemorySize, ATTN_DSMEM);

    convert_x_kernel<<<3072, 256>>>(x);         // launch 1
    convert_w_kernel<<<864, 256>>>(w_qkv);      // launch 2
    init_kernel<<<8, 1024>>>();                 // launch 3
    qkv_mma_kernel<<<dim3(18, 64), 512, QKV_DSMEM>>>();   // launch 4 (profiled)
    fixup_kernel<<<512, 256>>>(x, w_qkv);       // launch 5
    attn_kernel<<<dim3(16, 96), 256, ATTN_DSMEM>>>();     // launch 6
    proj_kernel<<<dim3(12, 128), 256>>>(w_proj, out);     // launch 7
}